// round 13
// baseline (speedup 1.0000x reference)
#include <cuda_runtime.h>
#include <cuda_fp16.h>
#include <cstdint>

#define N_NODES   150000
#define NUM_USERS 100000
#define DIM       64
#define NNZ_E     2400000
#define NNZ_PAD   2850000             // NNZ + 3*N_NODES upper bound (rows padded to x4)
#define BATCH     4096
#define HIST      50
#define UHIST     30
#define MC        5
#define CONCAT    192
#define INNER     384

#define SCAN_BLOCKS ((N_NODES + 1023) / 1024)   // 147

// fused spmm1 grid layout
#define SPMM_B  18750                 // ceil(150000*32/256)
#define MARK_O  (SPMM_B)              // 1024 blocks: 8 warps, 1 target/warp
#define UF_O    (MARK_O + 1024)       // 1024 blocks: 4 batch rows each
#define IF_O    (UF_O + 1024)
#define SW_O    (IF_O + 1024)         // 2304 blocks weight split
#define FUSED_GRID (SW_O + 2304)

// ---------------- device scratch ----------------
__device__ float g_l1[N_NODES * DIM];
__device__ float g_l2[N_NODES * DIM];
__device__ int   g_rowptr[N_NODES + 1];
__device__ int   g_wptr[N_NODES];
__device__ int   g_flag[N_NODES];
__device__ __align__(16) int   g_col[NNZ_PAD];
__device__ __align__(16) float g_val[NNZ_PAD];
__device__ int   g_bsum[256];
__device__ float g_uf[BATCH * CONCAT];
__device__ float g_itf[BATCH * CONCAT];
// fp16 split tensors
__device__ __align__(16) __half g_yhi[4 * BATCH * CONCAT];
__device__ __align__(16) __half g_ylo[4 * BATCH * CONCAT];
__device__ __align__(16) __half g_hhi[4 * BATCH * INNER];
__device__ __align__(16) __half g_hlo[4 * BATCH * INNER];
__device__ __align__(16) __half g_w1hi[4 * INNER * CONCAT];   // [v][n=384][k=192]
__device__ __align__(16) __half g_w1lo[4 * INNER * CONCAT];
__device__ __align__(16) __half g_w2hi[4 * CONCAT * INNER];   // [v][n=192][k=384]
__device__ __align__(16) __half g_w2lo[4 * CONCAT * INNER];

// ---------------- helpers ----------------
__device__ __forceinline__ uint32_t smem_u32(const void* p) {
    uint32_t a;
    asm("{ .reg .u64 t; cvta.to.shared.u64 t, %1; cvt.u32.u64 %0, t; }" : "=r"(a) : "l"(p));
    return a;
}
__device__ __forceinline__ void ldsm4(uint32_t& r0, uint32_t& r1, uint32_t& r2, uint32_t& r3,
                                      uint32_t addr) {
    asm volatile("ldmatrix.sync.aligned.m8n8.x4.shared.b16 {%0,%1,%2,%3}, [%4];"
                 : "=r"(r0), "=r"(r1), "=r"(r2), "=r"(r3) : "r"(addr));
}
__device__ __forceinline__ void mma16816(float* c, const uint32_t* a, const uint32_t* b) {
    asm volatile("mma.sync.aligned.m16n8k16.row.col.f32.f16.f16.f32 "
                 "{%0,%1,%2,%3},{%4,%5,%6,%7},{%8,%9},{%0,%1,%2,%3};"
                 : "+f"(c[0]), "+f"(c[1]), "+f"(c[2]), "+f"(c[3])
                 : "r"(a[0]), "r"(a[1]), "r"(a[2]), "r"(a[3]), "r"(b[0]), "r"(b[1]));
}
__device__ __forceinline__ void split2(float x, __half& hi, __half& lo) {
    hi = __float2half_rn(x);
    lo = __float2half_rn(x - __half2float(hi));
}

// ---------------- CSR build ----------------
__global__ void k_zero_cnt() {
    int i = blockIdx.x * blockDim.x + threadIdx.x;
    if (i < N_NODES) { g_wptr[i] = 0; g_flag[i] = 0; }
    if (i < NNZ_PAD) { g_col[i] = 0; g_val[i] = 0.f; }   // padding contributes 0 to SpMM
}
__global__ void k_hist(const int* __restrict__ rows) {
    int i = blockIdx.x * blockDim.x + threadIdx.x;
    if (i < NNZ_E) atomicAdd(&g_wptr[rows[i]], 1);
}
__global__ void k_scan_block() {
    __shared__ int s[1024];
    int tid = threadIdx.x;
    int i = blockIdx.x * 1024 + tid;
    int v = (i < N_NODES) ? ((g_wptr[i] + 3) & ~3) : 0;   // pad each row to multiple of 4
    s[tid] = v;
    __syncthreads();
    for (int off = 1; off < 1024; off <<= 1) {
        int t = (tid >= off) ? s[tid - off] : 0;
        __syncthreads();
        s[tid] += t;
        __syncthreads();
    }
    if (i < N_NODES) g_rowptr[i] = s[tid] - v;
    if (tid == 1023) g_bsum[blockIdx.x] = s[1023];
}
__global__ void k_scan_tops() {
    __shared__ int s[256];
    int tid = threadIdx.x;
    int v = (tid < SCAN_BLOCKS) ? g_bsum[tid] : 0;
    s[tid] = v;
    __syncthreads();
    for (int off = 1; off < 256; off <<= 1) {
        int t = (tid >= off) ? s[tid - off] : 0;
        __syncthreads();
        s[tid] += t;
        __syncthreads();
    }
    if (tid < SCAN_BLOCKS) g_bsum[tid] = s[tid];
}
__global__ void k_scan_add() {
    int i = blockIdx.x * blockDim.x + threadIdx.x;
    if (i < N_NODES) {
        int blk = i >> 10;
        int add = (blk > 0) ? g_bsum[blk - 1] : 0;
        int r = g_rowptr[i] + add;
        g_rowptr[i] = r;
        g_wptr[i] = r;
    }
    if (i == 0) g_rowptr[N_NODES] = g_bsum[SCAN_BLOCKS - 1];   // padded total
}
__global__ void k_scatter(const int* __restrict__ rows, const int* __restrict__ cols,
                          const float* __restrict__ vals) {
    int i = blockIdx.x * blockDim.x + threadIdx.x;
    if (i < NNZ_E) {
        int r = rows[i];
        int pos = atomicAdd(&g_wptr[r], 1);
        g_col[pos] = cols[i];
        g_val[pos] = vals[i];
    }
}

// ---------------- SpMM core: row padded to x4, aligned vector metadata loads ----------------
__device__ __forceinline__ float2 spmm_row(const float2* __restrict__ src, int row, int lane) {
    int s = g_rowptr[row], e = g_rowptr[row + 1];
    float2 a = make_float2(0.f, 0.f);
    for (int j = s; j < e; j += 4) {
        int4   c = *(const int4*)(g_col + j);
        float4 v = *(const float4*)(g_val + j);
        float2 x0 = src[c.x * 32 + lane];
        float2 x1 = src[c.y * 32 + lane];
        float2 x2 = src[c.z * 32 + lane];
        float2 x3 = src[c.w * 32 + lane];
        a.x += v.x * x0.x; a.y += v.x * x0.y;
        a.x += v.y * x1.x; a.y += v.y * x1.y;
        a.x += v.z * x2.x; a.y += v.z * x2.y;
        a.x += v.w * x3.x; a.y += v.w * x3.y;
    }
    return a;
}

// ---------------- FUSED: spmm layer1 + mark + history features + weight split ----------------
__global__ void k_spmm1_fused(const float2* __restrict__ emb2,
                              const float* __restrict__ emb,
                              const float* __restrict__ cate_tab,
                              const int* __restrict__ cates, const int* __restrict__ clens,
                              const int* __restrict__ users, const int* __restrict__ items,
                              const int* __restrict__ ihm, const int* __restrict__ ihl,
                              const int* __restrict__ uhm, const int* __restrict__ uhl,
                              const float* __restrict__ w1, const float* __restrict__ w2) {
    int blk = blockIdx.x;
    int tid = threadIdx.x;

    if (blk < SPMM_B) {
        int gtid = blk * 256 + tid;
        int row = gtid >> 5;
        int lane = gtid & 31;
        if (row >= N_NODES) return;
        float2 a = spmm_row(emb2, row, lane);
        ((float2*)g_l1)[row * 32 + lane] = a;
    } else if (blk < UF_O) {
        int t = (blk - MARK_O) * 8 + (tid >> 5);
        int lane = tid & 31;
        int row = (t < BATCH) ? users[t] : (NUM_USERS + items[t - BATCH]);
        if (lane == 0) g_flag[row] = 1;
        int s = g_rowptr[row], e = g_rowptr[row + 1];
        for (int j = s + lane; j < e; j += 32) g_flag[g_col[j]] = 1;   // padding marks row 0: harmless
    } else if (blk < IF_O) {
        int b = (blk - UF_O) * 4 + (tid >> 6);
        int d = tid & 63;
        int len = ihl[b];
        float si = 0.f, sc = 0.f;
        for (int h = 0; h < len; h++) {
            int it = ihm[b * HIST + h];
            si += emb[(it + NUM_USERS) * DIM + d];
            int cl = clens[it];
            float cs = 0.f;
            for (int c = 0; c < cl; c++)
                cs += cate_tab[cates[it * MC + c] * DIM + d];
            sc += cs / ((float)cl + 1e-9f);
        }
        float inv = 1.f / ((float)len + 1e-9f);
        g_uf[b * CONCAT + DIM + d]      = si * inv;
        g_uf[b * CONCAT + 2 * DIM + d]  = sc * inv;
    } else if (blk < SW_O) {
        int b = (blk - IF_O) * 4 + (tid >> 6);
        int d = tid & 63;
        int it = items[b];
        int cl = clens[it];
        float cs = 0.f;
        for (int c = 0; c < cl; c++)
            cs += cate_tab[cates[it * MC + c] * DIM + d];
        float avg_ic = cs / ((float)cl + 1e-9f);
        int len = uhl[b];
        float sh = 0.f;
        for (int h = 0; h < len; h++)
            sh += emb[uhm[b * UHIST + h] * DIM + d];
        g_itf[b * CONCAT + DIM + d]     = avg_ic;
        g_itf[b * CONCAT + 2 * DIM + d] = sh / ((float)len + 1e-9f);
    } else {
        int i = (blk - SW_O) * 256 + tid;
        const int C1 = 4 * INNER * CONCAT;
        if (i < C1) {
            int v = i / (INNER * CONCAT);
            int rem = i % (INNER * CONCAT);
            int n = rem / CONCAT;
            int k = rem % CONCAT;
            float x = w1[v * CONCAT * INNER + k * INNER + n];
            __half hi, lo; split2(x, hi, lo);
            g_w1hi[i] = hi; g_w1lo[i] = lo;
        } else if (i < 2 * C1) {
            int j = i - C1;
            int v = j / (CONCAT * INNER);
            int rem = j % (CONCAT * INNER);
            int n = rem / INNER;
            int k = rem % INNER;
            float x = w2[v * INNER * CONCAT + k * CONCAT + n];
            __half hi, lo; split2(x, hi, lo);
            g_w2hi[j] = hi; g_w2lo[j] = lo;
        }
    }
}

// ---------------- SpMM layer 2 (masked) ----------------
__global__ void k_spmm2() {
    int gtid = blockIdx.x * blockDim.x + threadIdx.x;
    int row = gtid >> 5;
    int lane = gtid & 31;
    if (row >= N_NODES) return;
    if (!g_flag[row]) return;
    float2 a = spmm_row((const float2*)g_l1, row, lane);
    ((float2*)g_l2)[row * 32 + lane] = a;
}

// ---------------- layer-3 at targets + static feature -> uf/itf cols 0..63 ----------------
__global__ void k_e3static(const float2* __restrict__ emb2,
                           const int* __restrict__ users, const int* __restrict__ items) {
    int gtid = blockIdx.x * blockDim.x + threadIdx.x;
    int t = gtid >> 5;
    int lane = gtid & 31;
    if (t >= 2 * BATCH) return;
    int row = (t < BATCH) ? users[t] : (NUM_USERS + items[t - BATCH]);
    float2 a = spmm_row((const float2*)g_l2, row, lane);
    int o = row * 32 + lane;
    float2 e0 = emb2[o];
    float2 e1 = ((const float2*)g_l1)[o];
    float2 e2 = ((const float2*)g_l2)[o];
    float2 r;
    r.x = (e0.x + e1.x + e2.x + a.x) * 0.25f;
    r.y = (e0.y + e1.y + e2.y + a.y) * 0.25f;
    if (t < BATCH) ((float2*)g_uf)[t * (CONCAT / 2) + lane] = r;
    else           ((float2*)g_itf)[(t - BATCH) * (CONCAT / 2) + lane] = r;
}

// ---------------- layernorm -> fp16 split y ----------------
__global__ void k_ln(const float* __restrict__ ln_w, const float* __restrict__ ln_b) {
    int v = blockIdx.y;
    int warp = threadIdx.x >> 5;
    int lane = threadIdx.x & 31;
    int row = blockIdx.x * 8 + warp;
    const float* x = ((v < 2) ? g_uf : g_itf) + row * CONCAT;

    float vals[6];
    float s = 0.f;
#pragma unroll
    for (int i = 0; i < 6; i++) { vals[i] = x[lane + 32 * i]; s += vals[i]; }
#pragma unroll
    for (int o = 16; o; o >>= 1) s += __shfl_xor_sync(0xffffffffu, s, o);
    float mu = s * (1.f / CONCAT);
    float vv = 0.f;
#pragma unroll
    for (int i = 0; i < 6; i++) { float dlt = vals[i] - mu; vv += dlt * dlt; }
#pragma unroll
    for (int o = 16; o; o >>= 1) vv += __shfl_xor_sync(0xffffffffu, vv, o);
    float rs = rsqrtf(vv * (1.f / CONCAT) + 1e-5f);

    int base = v * (BATCH * CONCAT) + row * CONCAT;
#pragma unroll
    for (int i = 0; i < 6; i++) {
        int c = lane + 32 * i;
        float y = (vals[i] - mu) * rs * ln_w[v * CONCAT + c] + ln_b[v * CONCAT + c];
        __half hi, lo; split2(y, hi, lo);
        g_yhi[base + c] = hi;
        g_ylo[base + c] = lo;
    }
}

// ---------------- HMMA GEMM1: H = relu(Y @ W1 + b1), K chunked for 2 CTAs/SM ----------------
// chunk = 96 cols (12 x 8 halves), row stride 208B. Ah@0 Al@26624 Bh@53248 Bl@79872.
#define G1_SMEM 106496
__global__ __launch_bounds__(256, 2) void k_gemm1_mma(const float* __restrict__ b1) {
    extern __shared__ __align__(16) char smem[];
    int tid = threadIdx.x, w = tid >> 5, lane = tid & 31;
    int v = blockIdx.z;
    int m0 = blockIdx.x * 128, n0 = blockIdx.y * 128;

    const __half* Ahg = g_yhi + v * (BATCH * CONCAT);
    const __half* Alg = g_ylo + v * (BATCH * CONCAT);
    const __half* Bhg = g_w1hi + v * (INNER * CONCAT);
    const __half* Blg = g_w1lo + v * (INNER * CONCAT);

    uint32_t sb = smem_u32(smem);
    int wm = (w >> 2) * 64, wn = (w & 3) * 32;
    float acc[4][4][4];
#pragma unroll
    for (int i = 0; i < 4; i++)
#pragma unroll
        for (int j = 0; j < 4; j++)
#pragma unroll
            for (int c = 0; c < 4; c++) acc[i][j][c] = 0.f;

    int lr = lane & 15;
    int lk2 = ((lane >> 4) * 8) * 2;

#pragma unroll 1
    for (int ch = 0; ch < 2; ch++) {
        if (ch) __syncthreads();
        int kl = ch * 96;
        for (int idx = tid; idx < 128 * 12; idx += 256) {
            int r = idx / 12, c8 = idx % 12;
            int d = r * 208 + c8 * 16;
            *(uint4*)(smem + d)         = *(const uint4*)(Ahg + (m0 + r) * CONCAT + kl + c8 * 8);
            *(uint4*)(smem + 26624 + d) = *(const uint4*)(Alg + (m0 + r) * CONCAT + kl + c8 * 8);
            *(uint4*)(smem + 53248 + d) = *(const uint4*)(Bhg + (n0 + r) * CONCAT + kl + c8 * 8);
            *(uint4*)(smem + 79872 + d) = *(const uint4*)(Blg + (n0 + r) * CONCAT + kl + c8 * 8);
        }
        __syncthreads();

#pragma unroll 1
        for (int ks = 0; ks < 6; ks++) {
            int k2 = ks * 32 + lk2;
            uint32_t ah[4][4], al[4][4], bh[4][2], bl[4][2];
#pragma unroll
            for (int i = 0; i < 4; i++) {
                uint32_t a = sb + (wm + 16 * i + lr) * 208 + k2;
                ldsm4(ah[i][0], ah[i][1], ah[i][2], ah[i][3], a);
                ldsm4(al[i][0], al[i][1], al[i][2], al[i][3], a + 26624);
            }
#pragma unroll
            for (int j2 = 0; j2 < 2; j2++) {
                uint32_t a = sb + 53248 + (wn + 16 * j2 + lr) * 208 + k2;
                uint32_t r0, r1, r2, r3;
                ldsm4(r0, r1, r2, r3, a);
                bh[2 * j2][0] = r0; bh[2 * j2][1] = r2;
                bh[2 * j2 + 1][0] = r1; bh[2 * j2 + 1][1] = r3;
                ldsm4(r0, r1, r2, r3, a + 26624);
                bl[2 * j2][0] = r0; bl[2 * j2][1] = r2;
                bl[2 * j2 + 1][0] = r1; bl[2 * j2 + 1][1] = r3;
            }
#pragma unroll
            for (int i = 0; i < 4; i++)
#pragma unroll
                for (int j = 0; j < 4; j++) {
                    mma16816(acc[i][j], ah[i], bh[j]);
                    mma16816(acc[i][j], ah[i], bl[j]);
                    mma16816(acc[i][j], al[i], bh[j]);
                }
        }
    }

    int r0 = lane >> 2, c0 = (lane & 3) * 2;
    __half* Hh = g_hhi + v * (BATCH * INNER);
    __half* Hl = g_hlo + v * (BATCH * INNER);
#pragma unroll
    for (int i = 0; i < 4; i++) {
#pragma unroll
        for (int j = 0; j < 4; j++) {
            int n = n0 + wn + 8 * j + c0;
            float bb0 = b1[v * INNER + n], bb1 = b1[v * INNER + n + 1];
#pragma unroll
            for (int half = 0; half < 2; half++) {
                int m = m0 + wm + 16 * i + r0 + 8 * half;
                float x0 = fmaxf(acc[i][j][2 * half] + bb0, 0.f);
                float x1 = fmaxf(acc[i][j][2 * half + 1] + bb1, 0.f);
                __half h0, l0, h1, l1;
                split2(x0, h0, l0);
                split2(x1, h1, l1);
                *(__half2*)(Hh + m * INNER + n) = __halves2half2(h0, h1);
                *(__half2*)(Hl + m * INNER + n) = __halves2half2(l0, l1);
            }
        }
    }
}

// ---------------- HMMA GEMM2: out = sum_v H_v @ W2_v + b2 + 2x, K chunked ----------------
// chunk = 96 cols, 8 chunks (2 variants x 384). Ah@0 Al@26624 Bh@53248 Bl@66560.
#define G2_SMEM 79872
__global__ __launch_bounds__(256, 2) void k_gemm2_mma(const float* __restrict__ b2,
                                                      float* __restrict__ out) {
    extern __shared__ __align__(16) char smem[];
    int tid = threadIdx.x, w = tid >> 5, lane = tid & 31;
    int z = blockIdx.z;
    int v0 = 2 * z;
    int m0 = blockIdx.x * 128, n0 = blockIdx.y * 64;

    uint32_t sb = smem_u32(smem);
    int wm = (w & 3) * 32, wn = (w >> 2) * 32;
    float acc[2][4][4];
#pragma unroll
    for (int i = 0; i < 2; i++)
#pragma unroll
        for (int j = 0; j < 4; j++)
#pragma unroll
            for (int c = 0; c < 4; c++) acc[i][j][c] = 0.f;

    int lr = lane & 15;
    int lk2 = ((lane >> 4) * 8) * 2;

#pragma unroll 1
    for (int cc = 0; cc < 8; cc++) {
        int v = v0 + (cc >> 2);
        int kl = (cc & 3) * 96;
        const __half* Ahg = g_hhi + v * (BATCH * INNER);
        const __half* Alg = g_hlo + v * (BATCH * INNER);
        const __half* Bhg = g_w2hi + v * (CONCAT * INNER);
        const __half* Blg = g_w2lo + v * (CONCAT * INNER);
        if (cc) __syncthreads();
        for (int idx = tid; idx < 128 * 12; idx += 256) {
            int r = idx / 12, c8 = idx % 12;
            int d = r * 208 + c8 * 16;
            *(uint4*)(smem + d)         = *(const uint4*)(Ahg + (m0 + r) * INNER + kl + c8 * 8);
            *(uint4*)(smem + 26624 + d) = *(const uint4*)(Alg + (m0 + r) * INNER + kl + c8 * 8);
        }
        for (int idx = tid; idx < 64 * 12; idx += 256) {
            int r = idx / 12, c8 = idx % 12;
            int d = r * 208 + c8 * 16;
            *(uint4*)(smem + 53248 + d) = *(const uint4*)(Bhg + (n0 + r) * INNER + kl + c8 * 8);
            *(uint4*)(smem + 66560 + d) = *(const uint4*)(Blg + (n0 + r) * INNER + kl + c8 * 8);
        }
        __syncthreads();

#pragma unroll 1
        for (int ks = 0; ks < 6; ks++) {
            int k2 = ks * 32 + lk2;
            uint32_t ah[2][4], al[2][4], bh[4][2], bl[4][2];
#pragma unroll
            for (int i = 0; i < 2; i++) {
                uint32_t a = sb + (wm + 16 * i + lr) * 208 + k2;
                ldsm4(ah[i][0], ah[i][1], ah[i][2], ah[i][3], a);
                ldsm4(al[i][0], al[i][1], al[i][2], al[i][3], a + 26624);
            }
#pragma unroll
            for (int j2 = 0; j2 < 2; j2++) {
                uint32_t a = sb + 53248 + (wn + 16 * j2 + lr) * 208 + k2;
                uint32_t r0, r1, r2, r3;
                ldsm4(r0, r1, r2, r3, a);
                bh[2 * j2][0] = r0; bh[2 * j2][1] = r2;
                bh[2 * j2 + 1][0] = r1; bh[2 * j2 + 1][1] = r3;
                ldsm4(r0, r1, r2, r3, a + 13312);
                bl[2 * j2][0] = r0; bl[2 * j2][1] = r2;
                bl[2 * j2 + 1][0] = r1; bl[2 * j2 + 1][1] = r3;
            }
#pragma unroll
            for (int i = 0; i < 2; i++)
#pragma unroll
                for (int j = 0; j < 4; j++) {
                    mma16816(acc[i][j], ah[i], bh[j]);
                    mma16816(acc[i][j], ah[i], bl[j]);
                    mma16816(acc[i][j], al[i], bh[j]);
                }
        }
    }

    int r0 = lane >> 2, c0 = (lane & 3) * 2;
    const float* xin = (z == 0) ? g_uf : g_itf;
    float* outz = out + z * (BATCH * CONCAT);
#pragma unroll
    for (int i = 0; i < 2; i++) {
#pragma unroll
        for (int j = 0; j < 4; j++) {
            int n = n0 + wn + 8 * j + c0;
            float bb0 = b2[v0 * CONCAT + n]     + b2[(v0 + 1) * CONCAT + n];
            float bb1 = b2[v0 * CONCAT + n + 1] + b2[(v0 + 1) * CONCAT + n + 1];
#pragma unroll
            for (int half = 0; half < 2; half++) {
                int m = m0 + wm + 16 * i + r0 + 8 * half;
                float2 val;
                val.x = acc[i][j][2 * half]     + bb0 + 2.f * xin[m * CONCAT + n];
                val.y = acc[i][j][2 * half + 1] + bb1 + 2.f * xin[m * CONCAT + n + 1];
                *(float2*)&outz[m * CONCAT + n] = val;
            }
        }
    }
}

// ---------------- row-normalize ----------------
__global__ void k_norm(float* __restrict__ out) {
    int warp = threadIdx.x >> 5;
    int lane = threadIdx.x & 31;
    int row = blockIdx.x * 8 + warp;
    if (row >= 2 * BATCH) return;
    float* x = out + row * CONCAT;
    float vals[6];
    float ss = 0.f;
#pragma unroll
    for (int i = 0; i < 6; i++) { vals[i] = x[lane + 32 * i]; ss += vals[i] * vals[i]; }
#pragma unroll
    for (int o = 16; o; o >>= 1) ss += __shfl_xor_sync(0xffffffffu, ss, o);
    float s = 1.f / fmaxf(sqrtf(ss), 1e-12f);
#pragma unroll
    for (int i = 0; i < 6; i++) x[lane + 32 * i] = vals[i] * s;
}

// ---------------- launch ----------------
extern "C" void kernel_launch(void* const* d_in, const int* in_sizes, int n_in,
                              void* d_out, int out_size) {
    const float* emb       = (const float*)d_in[0];
    const float* cate_tab  = (const float*)d_in[1];
    const float* adj_vals  = (const float*)d_in[2];
    const float* mlp_ln_w  = (const float*)d_in[3];
    const float* mlp_ln_b  = (const float*)d_in[4];
    const float* mlp_w1    = (const float*)d_in[5];
    const float* mlp_b1    = (const float*)d_in[6];
    const float* mlp_w2    = (const float*)d_in[7];
    const float* mlp_b2    = (const float*)d_in[8];
    const int*   adj_rows  = (const int*)d_in[9];
    const int*   adj_cols  = (const int*)d_in[10];
    const int*   cates     = (const int*)d_in[11];
    const int*   cate_lens = (const int*)d_in[12];
    const int*   users     = (const int*)d_in[13];
    const int*   items     = (const int*)d_in[14];
    const int*   ihm       = (const int*)d_in[15];
    const int*   ihl       = (const int*)d_in[16];
    const int*   uhm       = (const int*)d_in[17];
    const int*   uhl       = (const int*)d_in[18];
    float* out = (float*)d_out;

    cudaFuncSetAttribute(k_gemm1_mma, cudaFuncAttributeMaxDynamicSharedMemorySize, G1_SMEM);
    cudaFuncSetAttribute(k_gemm2_mma, cudaFuncAttributeMaxDynamicSharedMemorySize, G2_SMEM);

    // CSR build (zero includes col/val padding init)
    k_zero_cnt<<<(NNZ_PAD + 255) / 256, 256>>>();
    k_hist<<<(NNZ_E + 255) / 256, 256>>>(adj_rows);
    k_scan_block<<<SCAN_BLOCKS, 1024>>>();
    k_scan_tops<<<1, 256>>>();
    k_scan_add<<<(N_NODES + 255) / 256, 256>>>();
    k_scatter<<<(NNZ_E + 255) / 256, 256>>>(adj_rows, adj_cols, adj_vals);

    // fused: SpMM layer1 + mark + history features + weight split
    k_spmm1_fused<<<FUSED_GRID, 256>>>((const float2*)emb, emb, cate_tab, cates, cate_lens,
                                       users, items, ihm, ihl, uhm, uhl, mlp_w1, mlp_w2);
    // SpMM layer 2 (masked)
    k_spmm2<<<SPMM_B, 256>>>();
    // layer 3 at targets + static features
    k_e3static<<<(2 * BATCH * 32 + 255) / 256, 256>>>((const float2*)emb, users, items);

    // MLP on HMMA tensor cores
    k_ln<<<dim3(BATCH / 8, 4), 256>>>(mlp_ln_w, mlp_ln_b);
    k_gemm1_mma<<<dim3(BATCH / 128, INNER / 128, 4), 256, G1_SMEM>>>(mlp_b1);
    k_gemm2_mma<<<dim3(BATCH / 128, CONCAT / 64, 2), 256, G2_SMEM>>>(mlp_b2, out);
    k_norm<<<(2 * BATCH + 7) / 8, 256>>>(out);
}

// round 14
// speedup vs baseline: 1.1222x; 1.1222x over previous
#include <cuda_runtime.h>
#include <cuda_fp16.h>
#include <cstdint>

#define N_NODES   150000
#define NUM_USERS 100000
#define DIM       64
#define NNZ_E     2400000
#define BATCH     4096
#define HIST      50
#define UHIST     30
#define MC        5
#define CONCAT    192
#define INNER     384

#define SCAN_BLOCKS ((N_NODES + 1023) / 1024)   // 147

// fused hist grid: hist + weight split
#define HIST_B   9375
#define HSW_O    (HIST_B)
#define HIST_GRID (HSW_O + 2304)

// fused scatter grid: scatter + user feat + item feat
#define SCAT_B   9375
#define SUF_O    (SCAT_B)
#define SIF_O    (SUF_O + 1024)
#define SCAT_GRID (SIF_O + 1024)

// fused spmm1 grid: spmm + mark
#define SPMM_B   18750                // ceil(150000*32/256)
#define MARK_O   (SPMM_B)
#define SPMM_GRID (MARK_O + 1024)

// ---------------- device scratch ----------------
__device__ float g_l1[N_NODES * DIM];
__device__ float g_l2[N_NODES * DIM];
__device__ int   g_rowptr[N_NODES + 1];
__device__ int   g_wptr[N_NODES];
__device__ int   g_flag[N_NODES];
__device__ int   g_col[NNZ_E];
__device__ float g_val[NNZ_E];
__device__ int   g_bsum[256];
__device__ float g_uf[BATCH * CONCAT];
__device__ float g_itf[BATCH * CONCAT];
// fp16 split tensors
__device__ __align__(16) __half g_yhi[4 * BATCH * CONCAT];
__device__ __align__(16) __half g_ylo[4 * BATCH * CONCAT];
__device__ __align__(16) __half g_hhi[4 * BATCH * INNER];
__device__ __align__(16) __half g_hlo[4 * BATCH * INNER];
__device__ __align__(16) __half g_w1hi[4 * INNER * CONCAT];   // [v][n=384][k=192]
__device__ __align__(16) __half g_w1lo[4 * INNER * CONCAT];
__device__ __align__(16) __half g_w2hi[4 * CONCAT * INNER];   // [v][n=192][k=384]
__device__ __align__(16) __half g_w2lo[4 * CONCAT * INNER];

// ---------------- helpers ----------------
__device__ __forceinline__ uint32_t smem_u32(const void* p) {
    uint32_t a;
    asm("{ .reg .u64 t; cvta.to.shared.u64 t, %1; cvt.u32.u64 %0, t; }" : "=r"(a) : "l"(p));
    return a;
}
__device__ __forceinline__ void ldsm4(uint32_t& r0, uint32_t& r1, uint32_t& r2, uint32_t& r3,
                                      uint32_t addr) {
    asm volatile("ldmatrix.sync.aligned.m8n8.x4.shared.b16 {%0,%1,%2,%3}, [%4];"
                 : "=r"(r0), "=r"(r1), "=r"(r2), "=r"(r3) : "r"(addr));
}
__device__ __forceinline__ void mma16816(float* c, const uint32_t* a, const uint32_t* b) {
    asm volatile("mma.sync.aligned.m16n8k16.row.col.f32.f16.f16.f32 "
                 "{%0,%1,%2,%3},{%4,%5,%6,%7},{%8,%9},{%0,%1,%2,%3};"
                 : "+f"(c[0]), "+f"(c[1]), "+f"(c[2]), "+f"(c[3])
                 : "r"(a[0]), "r"(a[1]), "r"(a[2]), "r"(a[3]), "r"(b[0]), "r"(b[1]));
}
__device__ __forceinline__ void split2(float x, __half& hi, __half& lo) {
    hi = __float2half_rn(x);
    lo = __float2half_rn(x - __half2float(hi));
}

// ---------------- CSR build ----------------
__global__ void k_zero_cnt() {
    int i = blockIdx.x * blockDim.x + threadIdx.x;
    if (i < N_NODES) { g_wptr[i] = 0; g_flag[i] = 0; }
}

// hist + weight split fused
__global__ void k_hist_fused(const int* __restrict__ rows,
                             const float* __restrict__ w1, const float* __restrict__ w2) {
    int blk = blockIdx.x;
    int tid = threadIdx.x;
    if (blk < HIST_B) {
        int i = blk * 256 + tid;
        if (i < NNZ_E) atomicAdd(&g_wptr[rows[i]], 1);
    } else {
        int i = (blk - HSW_O) * 256 + tid;
        const int C1 = 4 * INNER * CONCAT;
        if (i < C1) {
            int v = i / (INNER * CONCAT);
            int rem = i % (INNER * CONCAT);
            int n = rem / CONCAT;
            int k = rem % CONCAT;
            float x = w1[v * CONCAT * INNER + k * INNER + n];
            __half hi, lo; split2(x, hi, lo);
            g_w1hi[i] = hi; g_w1lo[i] = lo;
        } else if (i < 2 * C1) {
            int j = i - C1;
            int v = j / (CONCAT * INNER);
            int rem = j % (CONCAT * INNER);
            int n = rem / INNER;
            int k = rem % INNER;
            float x = w2[v * INNER * CONCAT + k * CONCAT + n];
            __half hi, lo; split2(x, hi, lo);
            g_w2hi[j] = hi; g_w2lo[j] = lo;
        }
    }
}

__global__ void k_scan_block() {
    __shared__ int s[1024];
    int tid = threadIdx.x;
    int i = blockIdx.x * 1024 + tid;
    int v = (i < N_NODES) ? g_wptr[i] : 0;
    s[tid] = v;
    __syncthreads();
    for (int off = 1; off < 1024; off <<= 1) {
        int t = (tid >= off) ? s[tid - off] : 0;
        __syncthreads();
        s[tid] += t;
        __syncthreads();
    }
    if (i < N_NODES) g_rowptr[i] = s[tid] - v;
    if (tid == 1023) g_bsum[blockIdx.x] = s[1023];
}
__global__ void k_scan_tops() {
    __shared__ int s[256];
    int tid = threadIdx.x;
    int v = (tid < SCAN_BLOCKS) ? g_bsum[tid] : 0;
    s[tid] = v;
    __syncthreads();
    for (int off = 1; off < 256; off <<= 1) {
        int t = (tid >= off) ? s[tid - off] : 0;
        __syncthreads();
        s[tid] += t;
        __syncthreads();
    }
    if (tid < SCAN_BLOCKS) g_bsum[tid] = s[tid];
}
__global__ void k_scan_add() {
    int i = blockIdx.x * blockDim.x + threadIdx.x;
    if (i < N_NODES) {
        int blk = i >> 10;
        int add = (blk > 0) ? g_bsum[blk - 1] : 0;
        int r = g_rowptr[i] + add;
        g_rowptr[i] = r;
        g_wptr[i] = r;
    }
    if (i == 0) g_rowptr[N_NODES] = NNZ_E;
}

// scatter + user feat + item feat fused
__global__ void k_scatter_fused(const int* __restrict__ rows, const int* __restrict__ cols,
                                const float* __restrict__ vals,
                                const float* __restrict__ emb,
                                const float* __restrict__ cate_tab,
                                const int* __restrict__ cates, const int* __restrict__ clens,
                                const int* __restrict__ items,
                                const int* __restrict__ ihm, const int* __restrict__ ihl,
                                const int* __restrict__ uhm, const int* __restrict__ uhl) {
    int blk = blockIdx.x;
    int tid = threadIdx.x;
    if (blk < SCAT_B) {
        int i = blk * 256 + tid;
        if (i < NNZ_E) {
            int r = rows[i];
            int pos = atomicAdd(&g_wptr[r], 1);
            g_col[pos] = cols[i];
            g_val[pos] = vals[i];
        }
    } else if (blk < SIF_O) {
        // user history features (cols 64..191)
        int b = (blk - SUF_O) * 4 + (tid >> 6);
        int d = tid & 63;
        int len = ihl[b];
        float si = 0.f, sc = 0.f;
        for (int h = 0; h < len; h++) {
            int it = ihm[b * HIST + h];
            si += emb[(it + NUM_USERS) * DIM + d];
            int cl = clens[it];
            float cs = 0.f;
            for (int c = 0; c < cl; c++)
                cs += cate_tab[cates[it * MC + c] * DIM + d];
            sc += cs / ((float)cl + 1e-9f);
        }
        float inv = 1.f / ((float)len + 1e-9f);
        g_uf[b * CONCAT + DIM + d]      = si * inv;
        g_uf[b * CONCAT + 2 * DIM + d]  = sc * inv;
    } else {
        // item features (cols 64..191)
        int b = (blk - SIF_O) * 4 + (tid >> 6);
        int d = tid & 63;
        int it = items[b];
        int cl = clens[it];
        float cs = 0.f;
        for (int c = 0; c < cl; c++)
            cs += cate_tab[cates[it * MC + c] * DIM + d];
        float avg_ic = cs / ((float)cl + 1e-9f);
        int len = uhl[b];
        float sh = 0.f;
        for (int h = 0; h < len; h++)
            sh += emb[uhm[b * UHIST + h] * DIM + d];
        g_itf[b * CONCAT + DIM + d]     = avg_ic;
        g_itf[b * CONCAT + 2 * DIM + d] = sh / ((float)len + 1e-9f);
    }
}

// ---------------- SpMM core (warp computes one row) ----------------
__device__ __forceinline__ float2 spmm_row(const float2* __restrict__ src, int row, int lane) {
    int s = g_rowptr[row], e = g_rowptr[row + 1];
    float2 a = make_float2(0.f, 0.f);
    int j = s;
    for (; j + 3 < e; j += 4) {
        int c0 = g_col[j], c1 = g_col[j + 1], c2 = g_col[j + 2], c3 = g_col[j + 3];
        float v0 = g_val[j], v1 = g_val[j + 1], v2 = g_val[j + 2], v3 = g_val[j + 3];
        float2 x0 = src[c0 * 32 + lane];
        float2 x1 = src[c1 * 32 + lane];
        float2 x2 = src[c2 * 32 + lane];
        float2 x3 = src[c3 * 32 + lane];
        a.x += v0 * x0.x; a.y += v0 * x0.y;
        a.x += v1 * x1.x; a.y += v1 * x1.y;
        a.x += v2 * x2.x; a.y += v2 * x2.y;
        a.x += v3 * x3.x; a.y += v3 * x3.y;
    }
    for (; j < e; j++) {
        int c = g_col[j];
        float v = g_val[j];
        float2 x = src[c * 32 + lane];
        a.x += v * x.x; a.y += v * x.y;
    }
    return a;
}

// ---------------- FUSED: spmm layer1 + mark ----------------
__global__ void k_spmm1_fused(const float2* __restrict__ emb2,
                              const int* __restrict__ users, const int* __restrict__ items) {
    int blk = blockIdx.x;
    int tid = threadIdx.x;

    if (blk < SPMM_B) {
        int gtid = blk * 256 + tid;
        int row = gtid >> 5;
        int lane = gtid & 31;
        if (row >= N_NODES) return;
        float2 a = spmm_row(emb2, row, lane);
        ((float2*)g_l1)[row * 32 + lane] = a;
    } else {
        int t = (blk - MARK_O) * 8 + (tid >> 5);
        int lane = tid & 31;
        int row = (t < BATCH) ? users[t] : (NUM_USERS + items[t - BATCH]);
        if (lane == 0) g_flag[row] = 1;
        int s = g_rowptr[row], e = g_rowptr[row + 1];
        for (int j = s + lane; j < e; j += 32) g_flag[g_col[j]] = 1;
    }
}

// ---------------- SpMM layer 2 (masked) ----------------
__global__ void k_spmm2() {
    int gtid = blockIdx.x * blockDim.x + threadIdx.x;
    int row = gtid >> 5;
    int lane = gtid & 31;
    if (row >= N_NODES) return;
    if (!g_flag[row]) return;
    float2 a = spmm_row((const float2*)g_l1, row, lane);
    ((float2*)g_l2)[row * 32 + lane] = a;
}

// ---------------- layer-3 at targets + static feature -> uf/itf cols 0..63 ----------------
__global__ void k_e3static(const float2* __restrict__ emb2,
                           const int* __restrict__ users, const int* __restrict__ items) {
    int gtid = blockIdx.x * blockDim.x + threadIdx.x;
    int t = gtid >> 5;
    int lane = gtid & 31;
    if (t >= 2 * BATCH) return;
    int row = (t < BATCH) ? users[t] : (NUM_USERS + items[t - BATCH]);
    float2 a = spmm_row((const float2*)g_l2, row, lane);
    int o = row * 32 + lane;
    float2 e0 = emb2[o];
    float2 e1 = ((const float2*)g_l1)[o];
    float2 e2 = ((const float2*)g_l2)[o];
    float2 r;
    r.x = (e0.x + e1.x + e2.x + a.x) * 0.25f;
    r.y = (e0.y + e1.y + e2.y + a.y) * 0.25f;
    if (t < BATCH) ((float2*)g_uf)[t * (CONCAT / 2) + lane] = r;
    else           ((float2*)g_itf)[(t - BATCH) * (CONCAT / 2) + lane] = r;
}

// ---------------- layernorm -> fp16 split y ----------------
__global__ void k_ln(const float* __restrict__ ln_w, const float* __restrict__ ln_b) {
    int v = blockIdx.y;
    int warp = threadIdx.x >> 5;
    int lane = threadIdx.x & 31;
    int row = blockIdx.x * 8 + warp;
    const float* x = ((v < 2) ? g_uf : g_itf) + row * CONCAT;

    float vals[6];
    float s = 0.f;
#pragma unroll
    for (int i = 0; i < 6; i++) { vals[i] = x[lane + 32 * i]; s += vals[i]; }
#pragma unroll
    for (int o = 16; o; o >>= 1) s += __shfl_xor_sync(0xffffffffu, s, o);
    float mu = s * (1.f / CONCAT);
    float vv = 0.f;
#pragma unroll
    for (int i = 0; i < 6; i++) { float dlt = vals[i] - mu; vv += dlt * dlt; }
#pragma unroll
    for (int o = 16; o; o >>= 1) vv += __shfl_xor_sync(0xffffffffu, vv, o);
    float rs = rsqrtf(vv * (1.f / CONCAT) + 1e-5f);

    int base = v * (BATCH * CONCAT) + row * CONCAT;
#pragma unroll
    for (int i = 0; i < 6; i++) {
        int c = lane + 32 * i;
        float y = (vals[i] - mu) * rs * ln_w[v * CONCAT + c] + ln_b[v * CONCAT + c];
        __half hi, lo; split2(y, hi, lo);
        g_yhi[base + c] = hi;
        g_ylo[base + c] = lo;
    }
}

// ---------------- HMMA GEMM1: H = relu(Y @ W1 + b1), K chunked for 2 CTAs/SM ----------------
// chunk = 96 cols (12 x 8 halves), row stride 208B. Ah@0 Al@26624 Bh@53248 Bl@79872.
#define G1_SMEM 106496
__global__ __launch_bounds__(256, 2) void k_gemm1_mma(const float* __restrict__ b1) {
    extern __shared__ __align__(16) char smem[];
    int tid = threadIdx.x, w = tid >> 5, lane = tid & 31;
    int v = blockIdx.z;
    int m0 = blockIdx.x * 128, n0 = blockIdx.y * 128;

    const __half* Ahg = g_yhi + v * (BATCH * CONCAT);
    const __half* Alg = g_ylo + v * (BATCH * CONCAT);
    const __half* Bhg = g_w1hi + v * (INNER * CONCAT);
    const __half* Blg = g_w1lo + v * (INNER * CONCAT);

    uint32_t sb = smem_u32(smem);
    int wm = (w >> 2) * 64, wn = (w & 3) * 32;
    float acc[4][4][4];
#pragma unroll
    for (int i = 0; i < 4; i++)
#pragma unroll
        for (int j = 0; j < 4; j++)
#pragma unroll
            for (int c = 0; c < 4; c++) acc[i][j][c] = 0.f;

    int lr = lane & 15;
    int lk2 = ((lane >> 4) * 8) * 2;

#pragma unroll 1
    for (int ch = 0; ch < 2; ch++) {
        if (ch) __syncthreads();
        int kl = ch * 96;
        for (int idx = tid; idx < 128 * 12; idx += 256) {
            int r = idx / 12, c8 = idx % 12;
            int d = r * 208 + c8 * 16;
            *(uint4*)(smem + d)         = *(const uint4*)(Ahg + (m0 + r) * CONCAT + kl + c8 * 8);
            *(uint4*)(smem + 26624 + d) = *(const uint4*)(Alg + (m0 + r) * CONCAT + kl + c8 * 8);
            *(uint4*)(smem + 53248 + d) = *(const uint4*)(Bhg + (n0 + r) * CONCAT + kl + c8 * 8);
            *(uint4*)(smem + 79872 + d) = *(const uint4*)(Blg + (n0 + r) * CONCAT + kl + c8 * 8);
        }
        __syncthreads();

#pragma unroll 1
        for (int ks = 0; ks < 6; ks++) {
            int k2 = ks * 32 + lk2;
            uint32_t ah[4][4], al[4][4], bh[4][2], bl[4][2];
#pragma unroll
            for (int i = 0; i < 4; i++) {
                uint32_t a = sb + (wm + 16 * i + lr) * 208 + k2;
                ldsm4(ah[i][0], ah[i][1], ah[i][2], ah[i][3], a);
                ldsm4(al[i][0], al[i][1], al[i][2], al[i][3], a + 26624);
            }
#pragma unroll
            for (int j2 = 0; j2 < 2; j2++) {
                uint32_t a = sb + 53248 + (wn + 16 * j2 + lr) * 208 + k2;
                uint32_t r0, r1, r2, r3;
                ldsm4(r0, r1, r2, r3, a);
                bh[2 * j2][0] = r0; bh[2 * j2][1] = r2;
                bh[2 * j2 + 1][0] = r1; bh[2 * j2 + 1][1] = r3;
                ldsm4(r0, r1, r2, r3, a + 26624);
                bl[2 * j2][0] = r0; bl[2 * j2][1] = r2;
                bl[2 * j2 + 1][0] = r1; bl[2 * j2 + 1][1] = r3;
            }
#pragma unroll
            for (int i = 0; i < 4; i++)
#pragma unroll
                for (int j = 0; j < 4; j++) {
                    mma16816(acc[i][j], ah[i], bh[j]);
                    mma16816(acc[i][j], ah[i], bl[j]);
                    mma16816(acc[i][j], al[i], bh[j]);
                }
        }
    }

    int r0 = lane >> 2, c0 = (lane & 3) * 2;
    __half* Hh = g_hhi + v * (BATCH * INNER);
    __half* Hl = g_hlo + v * (BATCH * INNER);
#pragma unroll
    for (int i = 0; i < 4; i++) {
#pragma unroll
        for (int j = 0; j < 4; j++) {
            int n = n0 + wn + 8 * j + c0;
            float bb0 = b1[v * INNER + n], bb1 = b1[v * INNER + n + 1];
#pragma unroll
            for (int half = 0; half < 2; half++) {
                int m = m0 + wm + 16 * i + r0 + 8 * half;
                float x0 = fmaxf(acc[i][j][2 * half] + bb0, 0.f);
                float x1 = fmaxf(acc[i][j][2 * half + 1] + bb1, 0.f);
                __half h0, l0, h1, l1;
                split2(x0, h0, l0);
                split2(x1, h1, l1);
                *(__half2*)(Hh + m * INNER + n) = __halves2half2(h0, h1);
                *(__half2*)(Hl + m * INNER + n) = __halves2half2(l0, l1);
            }
        }
    }
}

// ---------------- HMMA GEMM2: out = sum_v H_v @ W2_v + b2 + 2x, K chunked ----------------
// chunk = 96 cols, 8 chunks (2 variants x 384). Ah@0 Al@26624 Bh@53248 Bl@66560.
#define G2_SMEM 79872
__global__ __launch_bounds__(256, 2) void k_gemm2_mma(const float* __restrict__ b2,
                                                      float* __restrict__ out) {
    extern __shared__ __align__(16) char smem[];
    int tid = threadIdx.x, w = tid >> 5, lane = tid & 31;
    int z = blockIdx.z;
    int v0 = 2 * z;
    int m0 = blockIdx.x * 128, n0 = blockIdx.y * 64;

    uint32_t sb = smem_u32(smem);
    int wm = (w & 3) * 32, wn = (w >> 2) * 32;
    float acc[2][4][4];
#pragma unroll
    for (int i = 0; i < 2; i++)
#pragma unroll
        for (int j = 0; j < 4; j++)
#pragma unroll
            for (int c = 0; c < 4; c++) acc[i][j][c] = 0.f;

    int lr = lane & 15;
    int lk2 = ((lane >> 4) * 8) * 2;

#pragma unroll 1
    for (int cc = 0; cc < 8; cc++) {
        int v = v0 + (cc >> 2);
        int kl = (cc & 3) * 96;
        const __half* Ahg = g_hhi + v * (BATCH * INNER);
        const __half* Alg = g_hlo + v * (BATCH * INNER);
        const __half* Bhg = g_w2hi + v * (CONCAT * INNER);
        const __half* Blg = g_w2lo + v * (CONCAT * INNER);
        if (cc) __syncthreads();
        for (int idx = tid; idx < 128 * 12; idx += 256) {
            int r = idx / 12, c8 = idx % 12;
            int d = r * 208 + c8 * 16;
            *(uint4*)(smem + d)         = *(const uint4*)(Ahg + (m0 + r) * INNER + kl + c8 * 8);
            *(uint4*)(smem + 26624 + d) = *(const uint4*)(Alg + (m0 + r) * INNER + kl + c8 * 8);
        }
        for (int idx = tid; idx < 64 * 12; idx += 256) {
            int r = idx / 12, c8 = idx % 12;
            int d = r * 208 + c8 * 16;
            *(uint4*)(smem + 53248 + d) = *(const uint4*)(Bhg + (n0 + r) * INNER + kl + c8 * 8);
            *(uint4*)(smem + 66560 + d) = *(const uint4*)(Blg + (n0 + r) * INNER + kl + c8 * 8);
        }
        __syncthreads();

#pragma unroll 1
        for (int ks = 0; ks < 6; ks++) {
            int k2 = ks * 32 + lk2;
            uint32_t ah[2][4], al[2][4], bh[4][2], bl[4][2];
#pragma unroll
            for (int i = 0; i < 2; i++) {
                uint32_t a = sb + (wm + 16 * i + lr) * 208 + k2;
                ldsm4(ah[i][0], ah[i][1], ah[i][2], ah[i][3], a);
                ldsm4(al[i][0], al[i][1], al[i][2], al[i][3], a + 26624);
            }
#pragma unroll
            for (int j2 = 0; j2 < 2; j2++) {
                uint32_t a = sb + 53248 + (wn + 16 * j2 + lr) * 208 + k2;
                uint32_t r0, r1, r2, r3;
                ldsm4(r0, r1, r2, r3, a);
                bh[2 * j2][0] = r0; bh[2 * j2][1] = r2;
                bh[2 * j2 + 1][0] = r1; bh[2 * j2 + 1][1] = r3;
                ldsm4(r0, r1, r2, r3, a + 13312);
                bl[2 * j2][0] = r0; bl[2 * j2][1] = r2;
                bl[2 * j2 + 1][0] = r1; bl[2 * j2 + 1][1] = r3;
            }
#pragma unroll
            for (int i = 0; i < 2; i++)
#pragma unroll
                for (int j = 0; j < 4; j++) {
                    mma16816(acc[i][j], ah[i], bh[j]);
                    mma16816(acc[i][j], ah[i], bl[j]);
                    mma16816(acc[i][j], al[i], bh[j]);
                }
        }
    }

    int r0 = lane >> 2, c0 = (lane & 3) * 2;
    const float* xin = (z == 0) ? g_uf : g_itf;
    float* outz = out + z * (BATCH * CONCAT);
#pragma unroll
    for (int i = 0; i < 2; i++) {
#pragma unroll
        for (int j = 0; j < 4; j++) {
            int n = n0 + wn + 8 * j + c0;
            float bb0 = b2[v0 * CONCAT + n]     + b2[(v0 + 1) * CONCAT + n];
            float bb1 = b2[v0 * CONCAT + n + 1] + b2[(v0 + 1) * CONCAT + n + 1];
#pragma unroll
            for (int half = 0; half < 2; half++) {
                int m = m0 + wm + 16 * i + r0 + 8 * half;
                float2 val;
                val.x = acc[i][j][2 * half]     + bb0 + 2.f * xin[m * CONCAT + n];
                val.y = acc[i][j][2 * half + 1] + bb1 + 2.f * xin[m * CONCAT + n + 1];
                *(float2*)&outz[m * CONCAT + n] = val;
            }
        }
    }
}

// ---------------- row-normalize ----------------
__global__ void k_norm(float* __restrict__ out) {
    int warp = threadIdx.x >> 5;
    int lane = threadIdx.x & 31;
    int row = blockIdx.x * 8 + warp;
    if (row >= 2 * BATCH) return;
    float* x = out + row * CONCAT;
    float vals[6];
    float ss = 0.f;
#pragma unroll
    for (int i = 0; i < 6; i++) { vals[i] = x[lane + 32 * i]; ss += vals[i] * vals[i]; }
#pragma unroll
    for (int o = 16; o; o >>= 1) ss += __shfl_xor_sync(0xffffffffu, ss, o);
    float s = 1.f / fmaxf(sqrtf(ss), 1e-12f);
#pragma unroll
    for (int i = 0; i < 6; i++) x[lane + 32 * i] = vals[i] * s;
}

// ---------------- launch ----------------
extern "C" void kernel_launch(void* const* d_in, const int* in_sizes, int n_in,
                              void* d_out, int out_size) {
    const float* emb       = (const float*)d_in[0];
    const float* cate_tab  = (const float*)d_in[1];
    const float* adj_vals  = (const float*)d_in[2];
    const float* mlp_ln_w  = (const float*)d_in[3];
    const float* mlp_ln_b  = (const float*)d_in[4];
    const float* mlp_w1    = (const float*)d_in[5];
    const float* mlp_b1    = (const float*)d_in[6];
    const float* mlp_w2    = (const float*)d_in[7];
    const float* mlp_b2    = (const float*)d_in[8];
    const int*   adj_rows  = (const int*)d_in[9];
    const int*   adj_cols  = (const int*)d_in[10];
    const int*   cates     = (const int*)d_in[11];
    const int*   cate_lens = (const int*)d_in[12];
    const int*   users     = (const int*)d_in[13];
    const int*   items     = (const int*)d_in[14];
    const int*   ihm       = (const int*)d_in[15];
    const int*   ihl       = (const int*)d_in[16];
    const int*   uhm       = (const int*)d_in[17];
    const int*   uhl       = (const int*)d_in[18];
    float* out = (float*)d_out;

    cudaFuncSetAttribute(k_gemm1_mma, cudaFuncAttributeMaxDynamicSharedMemorySize, G1_SMEM);
    cudaFuncSetAttribute(k_gemm2_mma, cudaFuncAttributeMaxDynamicSharedMemorySize, G2_SMEM);

    // CSR build (weight split hidden under hist; features hidden under scatter)
    k_zero_cnt<<<(N_NODES + 255) / 256, 256>>>();
    k_hist_fused<<<HIST_GRID, 256>>>(adj_rows, mlp_w1, mlp_w2);
    k_scan_block<<<SCAN_BLOCKS, 1024>>>();
    k_scan_tops<<<1, 256>>>();
    k_scan_add<<<(N_NODES + 255) / 256, 256>>>();
    k_scatter_fused<<<SCAT_GRID, 256>>>(adj_rows, adj_cols, adj_vals, emb, cate_tab,
                                        cates, cate_lens, items, ihm, ihl, uhm, uhl);

    // fused: SpMM layer1 + mark
    k_spmm1_fused<<<SPMM_GRID, 256>>>((const float2*)emb, users, items);
    // SpMM layer 2 (masked)
    k_spmm2<<<SPMM_B, 256>>>();
    // layer 3 at targets + static features
    k_e3static<<<(2 * BATCH * 32 + 255) / 256, 256>>>((const float2*)emb, users, items);

    // MLP on HMMA tensor cores
    k_ln<<<dim3(BATCH / 8, 4), 256>>>(mlp_ln_w, mlp_ln_b);
    k_gemm1_mma<<<dim3(BATCH / 128, INNER / 128, 4), 256, G1_SMEM>>>(mlp_b1);
    k_gemm2_mma<<<dim3(BATCH / 128, CONCAT / 64, 2), 256, G2_SMEM>>>(mlp_b2, out);
    k_norm<<<(2 * BATCH + 7) / 8, 256>>>(out);
}

// round 15
// speedup vs baseline: 1.1238x; 1.0014x over previous
#include <cuda_runtime.h>
#include <cuda_fp16.h>
#include <cstdint>

#define N_NODES   150000
#define NUM_USERS 100000
#define DIM       64
#define NNZ_E     2400000
#define BATCH     4096
#define HIST      50
#define UHIST     30
#define MC        5
#define CONCAT    192
#define INNER     384

#define SCAN_BLOCKS ((N_NODES + 1023) / 1024)   // 147

// fused spmm1 grid layout
#define SPMM_B  18750                 // ceil(150000*32/256)
#define MARK_O  (SPMM_B)              // 1024 blocks: 8 warps, 1 target/warp
#define UF_O    (MARK_O + 1024)       // 1024 blocks: 4 batch rows each
#define IF_O    (UF_O + 1024)
#define SW_O    (IF_O + 1024)         // 2304 blocks weight split
#define FUSED_GRID (SW_O + 2304)

// ---------------- device scratch ----------------
__device__ float g_l1[N_NODES * DIM];
__device__ float g_l2[N_NODES * DIM];
__device__ int   g_rowptr[N_NODES + 1];
__device__ int   g_wptr[N_NODES];
__device__ int   g_flag[N_NODES];
__device__ int   g_col[NNZ_E];
__device__ float g_val[NNZ_E];
__device__ int   g_bsum[256];
__device__ float g_uf[BATCH * CONCAT];
__device__ float g_itf[BATCH * CONCAT];
// fp16 split tensors
__device__ __align__(16) __half g_yhi[4 * BATCH * CONCAT];
__device__ __align__(16) __half g_ylo[4 * BATCH * CONCAT];
__device__ __align__(16) __half g_hhi[4 * BATCH * INNER];
__device__ __align__(16) __half g_hlo[4 * BATCH * INNER];
__device__ __align__(16) __half g_w1hi[4 * INNER * CONCAT];   // [v][n=384][k=192]
__device__ __align__(16) __half g_w1lo[4 * INNER * CONCAT];
__device__ __align__(16) __half g_w2hi[4 * CONCAT * INNER];   // [v][n=192][k=384]
__device__ __align__(16) __half g_w2lo[4 * CONCAT * INNER];

// ---------------- helpers ----------------
__device__ __forceinline__ uint32_t smem_u32(const void* p) {
    uint32_t a;
    asm("{ .reg .u64 t; cvta.to.shared.u64 t, %1; cvt.u32.u64 %0, t; }" : "=r"(a) : "l"(p));
    return a;
}
__device__ __forceinline__ void ldsm4(uint32_t& r0, uint32_t& r1, uint32_t& r2, uint32_t& r3,
                                      uint32_t addr) {
    asm volatile("ldmatrix.sync.aligned.m8n8.x4.shared.b16 {%0,%1,%2,%3}, [%4];"
                 : "=r"(r0), "=r"(r1), "=r"(r2), "=r"(r3) : "r"(addr));
}
__device__ __forceinline__ void mma16816(float* c, const uint32_t* a, const uint32_t* b) {
    asm volatile("mma.sync.aligned.m16n8k16.row.col.f32.f16.f16.f32 "
                 "{%0,%1,%2,%3},{%4,%5,%6,%7},{%8,%9},{%0,%1,%2,%3};"
                 : "+f"(c[0]), "+f"(c[1]), "+f"(c[2]), "+f"(c[3])
                 : "r"(a[0]), "r"(a[1]), "r"(a[2]), "r"(a[3]), "r"(b[0]), "r"(b[1]));
}
__device__ __forceinline__ void split2(float x, __half& hi, __half& lo) {
    hi = __float2half_rn(x);
    lo = __float2half_rn(x - __half2float(hi));
}

// ---------------- CSR build (champion scalar versions) ----------------
__global__ void k_zero_cnt() {
    int i = blockIdx.x * blockDim.x + threadIdx.x;
    if (i < N_NODES) { g_wptr[i] = 0; g_flag[i] = 0; }
}
__global__ void k_hist(const int* __restrict__ rows) {
    int i = blockIdx.x * blockDim.x + threadIdx.x;
    if (i < NNZ_E) atomicAdd(&g_wptr[rows[i]], 1);
}
__global__ void k_scan_block() {
    __shared__ int s[1024];
    int tid = threadIdx.x;
    int i = blockIdx.x * 1024 + tid;
    int v = (i < N_NODES) ? g_wptr[i] : 0;
    s[tid] = v;
    __syncthreads();
    for (int off = 1; off < 1024; off <<= 1) {
        int t = (tid >= off) ? s[tid - off] : 0;
        __syncthreads();
        s[tid] += t;
        __syncthreads();
    }
    if (i < N_NODES) g_rowptr[i] = s[tid] - v;
    if (tid == 1023) g_bsum[blockIdx.x] = s[1023];
}
__global__ void k_scan_tops() {
    __shared__ int s[256];
    int tid = threadIdx.x;
    int v = (tid < SCAN_BLOCKS) ? g_bsum[tid] : 0;
    s[tid] = v;
    __syncthreads();
    for (int off = 1; off < 256; off <<= 1) {
        int t = (tid >= off) ? s[tid - off] : 0;
        __syncthreads();
        s[tid] += t;
        __syncthreads();
    }
    if (tid < SCAN_BLOCKS) g_bsum[tid] = s[tid];
}
__global__ void k_scan_add() {
    int i = blockIdx.x * blockDim.x + threadIdx.x;
    if (i < N_NODES) {
        int blk = i >> 10;
        int add = (blk > 0) ? g_bsum[blk - 1] : 0;
        int r = g_rowptr[i] + add;
        g_rowptr[i] = r;
        g_wptr[i] = r;
    }
    if (i == 0) g_rowptr[N_NODES] = NNZ_E;
}
__global__ void k_scatter(const int* __restrict__ rows, const int* __restrict__ cols,
                          const float* __restrict__ vals) {
    int i = blockIdx.x * blockDim.x + threadIdx.x;
    if (i < NNZ_E) {
        int r = rows[i];
        int pos = atomicAdd(&g_wptr[r], 1);
        g_col[pos] = cols[i];
        g_val[pos] = vals[i];
    }
}

// ---------------- SpMM core (warp computes one row) ----------------
__device__ __forceinline__ float2 spmm_row(const float2* __restrict__ src, int row, int lane) {
    int s = g_rowptr[row], e = g_rowptr[row + 1];
    float2 a = make_float2(0.f, 0.f);
    int j = s;
    for (; j + 3 < e; j += 4) {
        int c0 = g_col[j], c1 = g_col[j + 1], c2 = g_col[j + 2], c3 = g_col[j + 3];
        float v0 = g_val[j], v1 = g_val[j + 1], v2 = g_val[j + 2], v3 = g_val[j + 3];
        float2 x0 = src[c0 * 32 + lane];
        float2 x1 = src[c1 * 32 + lane];
        float2 x2 = src[c2 * 32 + lane];
        float2 x3 = src[c3 * 32 + lane];
        a.x += v0 * x0.x; a.y += v0 * x0.y;
        a.x += v1 * x1.x; a.y += v1 * x1.y;
        a.x += v2 * x2.x; a.y += v2 * x2.y;
        a.x += v3 * x3.x; a.y += v3 * x3.y;
    }
    for (; j < e; j++) {
        int c = g_col[j];
        float v = g_val[j];
        float2 x = src[c * 32 + lane];
        a.x += v * x.x; a.y += v * x.y;
    }
    return a;
}

// ---------------- FUSED: spmm layer1 + mark + history features + weight split ----------------
__global__ void k_spmm1_fused(const float2* __restrict__ emb2,
                              const float* __restrict__ emb,
                              const float* __restrict__ cate_tab,
                              const int* __restrict__ cates, const int* __restrict__ clens,
                              const int* __restrict__ users, const int* __restrict__ items,
                              const int* __restrict__ ihm, const int* __restrict__ ihl,
                              const int* __restrict__ uhm, const int* __restrict__ uhl,
                              const float* __restrict__ w1, const float* __restrict__ w2) {
    int blk = blockIdx.x;
    int tid = threadIdx.x;

    if (blk < SPMM_B) {
        int gtid = blk * 256 + tid;
        int row = gtid >> 5;
        int lane = gtid & 31;
        if (row >= N_NODES) return;
        float2 a = spmm_row(emb2, row, lane);
        ((float2*)g_l1)[row * 32 + lane] = a;
    } else if (blk < UF_O) {
        int t = (blk - MARK_O) * 8 + (tid >> 5);
        int lane = tid & 31;
        int row = (t < BATCH) ? users[t] : (NUM_USERS + items[t - BATCH]);
        if (lane == 0) g_flag[row] = 1;
        int s = g_rowptr[row], e = g_rowptr[row + 1];
        for (int j = s + lane; j < e; j += 32) g_flag[g_col[j]] = 1;
    } else if (blk < IF_O) {
        int b = (blk - UF_O) * 4 + (tid >> 6);
        int d = tid & 63;
        int len = ihl[b];
        float si = 0.f, sc = 0.f;
        for (int h = 0; h < len; h++) {
            int it = ihm[b * HIST + h];
            si += emb[(it + NUM_USERS) * DIM + d];
            int cl = clens[it];
            float cs = 0.f;
            for (int c = 0; c < cl; c++)
                cs += cate_tab[cates[it * MC + c] * DIM + d];
            sc += cs / ((float)cl + 1e-9f);
        }
        float inv = 1.f / ((float)len + 1e-9f);
        g_uf[b * CONCAT + DIM + d]      = si * inv;
        g_uf[b * CONCAT + 2 * DIM + d]  = sc * inv;
    } else if (blk < SW_O) {
        int b = (blk - IF_O) * 4 + (tid >> 6);
        int d = tid & 63;
        int it = items[b];
        int cl = clens[it];
        float cs = 0.f;
        for (int c = 0; c < cl; c++)
            cs += cate_tab[cates[it * MC + c] * DIM + d];
        float avg_ic = cs / ((float)cl + 1e-9f);
        int len = uhl[b];
        float sh = 0.f;
        for (int h = 0; h < len; h++)
            sh += emb[uhm[b * UHIST + h] * DIM + d];
        g_itf[b * CONCAT + DIM + d]     = avg_ic;
        g_itf[b * CONCAT + 2 * DIM + d] = sh / ((float)len + 1e-9f);
    } else {
        int i = (blk - SW_O) * 256 + tid;
        const int C1 = 4 * INNER * CONCAT;
        if (i < C1) {
            int v = i / (INNER * CONCAT);
            int rem = i % (INNER * CONCAT);
            int n = rem / CONCAT;
            int k = rem % CONCAT;
            float x = w1[v * CONCAT * INNER + k * INNER + n];
            __half hi, lo; split2(x, hi, lo);
            g_w1hi[i] = hi; g_w1lo[i] = lo;
        } else if (i < 2 * C1) {
            int j = i - C1;
            int v = j / (CONCAT * INNER);
            int rem = j % (CONCAT * INNER);
            int n = rem / INNER;
            int k = rem % INNER;
            float x = w2[v * INNER * CONCAT + k * CONCAT + n];
            __half hi, lo; split2(x, hi, lo);
            g_w2hi[j] = hi; g_w2lo[j] = lo;
        }
    }
}

// ---------------- SpMM layer 2 (masked) ----------------
__global__ void k_spmm2() {
    int gtid = blockIdx.x * blockDim.x + threadIdx.x;
    int row = gtid >> 5;
    int lane = gtid & 31;
    if (row >= N_NODES) return;
    if (!g_flag[row]) return;
    float2 a = spmm_row((const float2*)g_l1, row, lane);
    ((float2*)g_l2)[row * 32 + lane] = a;
}

// ---------------- layer-3 at targets + static feature -> uf/itf cols 0..63 ----------------
__global__ void k_e3static(const float2* __restrict__ emb2,
                           const int* __restrict__ users, const int* __restrict__ items) {
    int gtid = blockIdx.x * blockDim.x + threadIdx.x;
    int t = gtid >> 5;
    int lane = gtid & 31;
    if (t >= 2 * BATCH) return;
    int row = (t < BATCH) ? users[t] : (NUM_USERS + items[t - BATCH]);
    float2 a = spmm_row((const float2*)g_l2, row, lane);
    int o = row * 32 + lane;
    float2 e0 = emb2[o];
    float2 e1 = ((const float2*)g_l1)[o];
    float2 e2 = ((const float2*)g_l2)[o];
    float2 r;
    r.x = (e0.x + e1.x + e2.x + a.x) * 0.25f;
    r.y = (e0.y + e1.y + e2.y + a.y) * 0.25f;
    if (t < BATCH) ((float2*)g_uf)[t * (CONCAT / 2) + lane] = r;
    else           ((float2*)g_itf)[(t - BATCH) * (CONCAT / 2) + lane] = r;
}

// ---------------- layernorm -> fp16 split y ----------------
__global__ void k_ln(const float* __restrict__ ln_w, const float* __restrict__ ln_b) {
    int v = blockIdx.y;
    int warp = threadIdx.x >> 5;
    int lane = threadIdx.x & 31;
    int row = blockIdx.x * 8 + warp;
    const float* x = ((v < 2) ? g_uf : g_itf) + row * CONCAT;

    float vals[6];
    float s = 0.f;
#pragma unroll
    for (int i = 0; i < 6; i++) { vals[i] = x[lane + 32 * i]; s += vals[i]; }
#pragma unroll
    for (int o = 16; o; o >>= 1) s += __shfl_xor_sync(0xffffffffu, s, o);
    float mu = s * (1.f / CONCAT);
    float vv = 0.f;
#pragma unroll
    for (int i = 0; i < 6; i++) { float dlt = vals[i] - mu; vv += dlt * dlt; }
#pragma unroll
    for (int o = 16; o; o >>= 1) vv += __shfl_xor_sync(0xffffffffu, vv, o);
    float rs = rsqrtf(vv * (1.f / CONCAT) + 1e-5f);

    int base = v * (BATCH * CONCAT) + row * CONCAT;
#pragma unroll
    for (int i = 0; i < 6; i++) {
        int c = lane + 32 * i;
        float y = (vals[i] - mu) * rs * ln_w[v * CONCAT + c] + ln_b[v * CONCAT + c];
        __half hi, lo; split2(y, hi, lo);
        g_yhi[base + c] = hi;
        g_ylo[base + c] = lo;
    }
}

// ---------------- HMMA GEMM1: H = relu(Y @ W1 + b1) ----------------
// Retiled 128x64 (GEMM2 shape): K=192 in 2 chunks of 96. Grid 32 x 6 x 4 = 768 CTAs.
// smem: Ah@0 Al@26624 Bh@53248 Bl@66560, total 79872. 2 CTAs/SM.
#define G1_SMEM 79872
__global__ __launch_bounds__(256, 2) void k_gemm1_mma(const float* __restrict__ b1) {
    extern __shared__ __align__(16) char smem[];
    int tid = threadIdx.x, w = tid >> 5, lane = tid & 31;
    int v = blockIdx.z;
    int m0 = blockIdx.x * 128, n0 = blockIdx.y * 64;

    const __half* Ahg = g_yhi + v * (BATCH * CONCAT);
    const __half* Alg = g_ylo + v * (BATCH * CONCAT);
    const __half* Bhg = g_w1hi + v * (INNER * CONCAT);
    const __half* Blg = g_w1lo + v * (INNER * CONCAT);

    uint32_t sb = smem_u32(smem);
    int wm = (w & 3) * 32, wn = (w >> 2) * 32;
    float acc[2][4][4];
#pragma unroll
    for (int i = 0; i < 2; i++)
#pragma unroll
        for (int j = 0; j < 4; j++)
#pragma unroll
            for (int c = 0; c < 4; c++) acc[i][j][c] = 0.f;

    int lr = lane & 15;
    int lk2 = ((lane >> 4) * 8) * 2;

#pragma unroll 1
    for (int ch = 0; ch < 2; ch++) {
        if (ch) __syncthreads();
        int kl = ch * 96;
        for (int idx = tid; idx < 128 * 12; idx += 256) {
            int r = idx / 12, c8 = idx % 12;
            int d = r * 208 + c8 * 16;
            *(uint4*)(smem + d)         = *(const uint4*)(Ahg + (m0 + r) * CONCAT + kl + c8 * 8);
            *(uint4*)(smem + 26624 + d) = *(const uint4*)(Alg + (m0 + r) * CONCAT + kl + c8 * 8);
        }
        for (int idx = tid; idx < 64 * 12; idx += 256) {
            int r = idx / 12, c8 = idx % 12;
            int d = r * 208 + c8 * 16;
            *(uint4*)(smem + 53248 + d) = *(const uint4*)(Bhg + (n0 + r) * CONCAT + kl + c8 * 8);
            *(uint4*)(smem + 66560 + d) = *(const uint4*)(Blg + (n0 + r) * CONCAT + kl + c8 * 8);
        }
        __syncthreads();

#pragma unroll 1
        for (int ks = 0; ks < 6; ks++) {
            int k2 = ks * 32 + lk2;
            uint32_t ah[2][4], al[2][4], bh[4][2], bl[4][2];
#pragma unroll
            for (int i = 0; i < 2; i++) {
                uint32_t a = sb + (wm + 16 * i + lr) * 208 + k2;
                ldsm4(ah[i][0], ah[i][1], ah[i][2], ah[i][3], a);
                ldsm4(al[i][0], al[i][1], al[i][2], al[i][3], a + 26624);
            }
#pragma unroll
            for (int j2 = 0; j2 < 2; j2++) {
                uint32_t a = sb + 53248 + (wn + 16 * j2 + lr) * 208 + k2;
                uint32_t r0, r1, r2, r3;
                ldsm4(r0, r1, r2, r3, a);
                bh[2 * j2][0] = r0; bh[2 * j2][1] = r2;
                bh[2 * j2 + 1][0] = r1; bh[2 * j2 + 1][1] = r3;
                ldsm4(r0, r1, r2, r3, a + 13312);
                bl[2 * j2][0] = r0; bl[2 * j2][1] = r2;
                bl[2 * j2 + 1][0] = r1; bl[2 * j2 + 1][1] = r3;
            }
#pragma unroll
            for (int i = 0; i < 2; i++)
#pragma unroll
                for (int j = 0; j < 4; j++) {
                    mma16816(acc[i][j], ah[i], bh[j]);
                    mma16816(acc[i][j], ah[i], bl[j]);
                    mma16816(acc[i][j], al[i], bh[j]);
                }
        }
    }

    int r0 = lane >> 2, c0 = (lane & 3) * 2;
    __half* Hh = g_hhi + v * (BATCH * INNER);
    __half* Hl = g_hlo + v * (BATCH * INNER);
#pragma unroll
    for (int i = 0; i < 2; i++) {
#pragma unroll
        for (int j = 0; j < 4; j++) {
            int n = n0 + wn + 8 * j + c0;
            float bb0 = b1[v * INNER + n], bb1 = b1[v * INNER + n + 1];
#pragma unroll
            for (int half = 0; half < 2; half++) {
                int m = m0 + wm + 16 * i + r0 + 8 * half;
                float x0 = fmaxf(acc[i][j][2 * half] + bb0, 0.f);
                float x1 = fmaxf(acc[i][j][2 * half + 1] + bb1, 0.f);
                __half h0, l0, h1, l1;
                split2(x0, h0, l0);
                split2(x1, h1, l1);
                *(__half2*)(Hh + m * INNER + n) = __halves2half2(h0, h1);
                *(__half2*)(Hl + m * INNER + n) = __halves2half2(l0, l1);
            }
        }
    }
}

// ---------------- HMMA GEMM2: out = sum_v H_v @ W2_v + b2 + 2x, K chunked ----------------
// chunk = 96 cols, 8 chunks (2 variants x 384). Ah@0 Al@26624 Bh@53248 Bl@66560.
#define G2_SMEM 79872
__global__ __launch_bounds__(256, 2) void k_gemm2_mma(const float* __restrict__ b2,
                                                      float* __restrict__ out) {
    extern __shared__ __align__(16) char smem[];
    int tid = threadIdx.x, w = tid >> 5, lane = tid & 31;
    int z = blockIdx.z;
    int v0 = 2 * z;
    int m0 = blockIdx.x * 128, n0 = blockIdx.y * 64;

    uint32_t sb = smem_u32(smem);
    int wm = (w & 3) * 32, wn = (w >> 2) * 32;
    float acc[2][4][4];
#pragma unroll
    for (int i = 0; i < 2; i++)
#pragma unroll
        for (int j = 0; j < 4; j++)
#pragma unroll
            for (int c = 0; c < 4; c++) acc[i][j][c] = 0.f;

    int lr = lane & 15;
    int lk2 = ((lane >> 4) * 8) * 2;

#pragma unroll 1
    for (int cc = 0; cc < 8; cc++) {
        int v = v0 + (cc >> 2);
        int kl = (cc & 3) * 96;
        const __half* Ahg = g_hhi + v * (BATCH * INNER);
        const __half* Alg = g_hlo + v * (BATCH * INNER);
        const __half* Bhg = g_w2hi + v * (CONCAT * INNER);
        const __half* Blg = g_w2lo + v * (CONCAT * INNER);
        if (cc) __syncthreads();
        for (int idx = tid; idx < 128 * 12; idx += 256) {
            int r = idx / 12, c8 = idx % 12;
            int d = r * 208 + c8 * 16;
            *(uint4*)(smem + d)         = *(const uint4*)(Ahg + (m0 + r) * INNER + kl + c8 * 8);
            *(uint4*)(smem + 26624 + d) = *(const uint4*)(Alg + (m0 + r) * INNER + kl + c8 * 8);
        }
        for (int idx = tid; idx < 64 * 12; idx += 256) {
            int r = idx / 12, c8 = idx % 12;
            int d = r * 208 + c8 * 16;
            *(uint4*)(smem + 53248 + d) = *(const uint4*)(Bhg + (n0 + r) * INNER + kl + c8 * 8);
            *(uint4*)(smem + 66560 + d) = *(const uint4*)(Blg + (n0 + r) * INNER + kl + c8 * 8);
        }
        __syncthreads();

#pragma unroll 1
        for (int ks = 0; ks < 6; ks++) {
            int k2 = ks * 32 + lk2;
            uint32_t ah[2][4], al[2][4], bh[4][2], bl[4][2];
#pragma unroll
            for (int i = 0; i < 2; i++) {
                uint32_t a = sb + (wm + 16 * i + lr) * 208 + k2;
                ldsm4(ah[i][0], ah[i][1], ah[i][2], ah[i][3], a);
                ldsm4(al[i][0], al[i][1], al[i][2], al[i][3], a + 26624);
            }
#pragma unroll
            for (int j2 = 0; j2 < 2; j2++) {
                uint32_t a = sb + 53248 + (wn + 16 * j2 + lr) * 208 + k2;
                uint32_t r0, r1, r2, r3;
                ldsm4(r0, r1, r2, r3, a);
                bh[2 * j2][0] = r0; bh[2 * j2][1] = r2;
                bh[2 * j2 + 1][0] = r1; bh[2 * j2 + 1][1] = r3;
                ldsm4(r0, r1, r2, r3, a + 13312);
                bl[2 * j2][0] = r0; bl[2 * j2][1] = r2;
                bl[2 * j2 + 1][0] = r1; bl[2 * j2 + 1][1] = r3;
            }
#pragma unroll
            for (int i = 0; i < 2; i++)
#pragma unroll
                for (int j = 0; j < 4; j++) {
                    mma16816(acc[i][j], ah[i], bh[j]);
                    mma16816(acc[i][j], ah[i], bl[j]);
                    mma16816(acc[i][j], al[i], bh[j]);
                }
        }
    }

    int r0 = lane >> 2, c0 = (lane & 3) * 2;
    const float* xin = (z == 0) ? g_uf : g_itf;
    float* outz = out + z * (BATCH * CONCAT);
#pragma unroll
    for (int i = 0; i < 2; i++) {
#pragma unroll
        for (int j = 0; j < 4; j++) {
            int n = n0 + wn + 8 * j + c0;
            float bb0 = b2[v0 * CONCAT + n]     + b2[(v0 + 1) * CONCAT + n];
            float bb1 = b2[v0 * CONCAT + n + 1] + b2[(v0 + 1) * CONCAT + n + 1];
#pragma unroll
            for (int half = 0; half < 2; half++) {
                int m = m0 + wm + 16 * i + r0 + 8 * half;
                float2 val;
                val.x = acc[i][j][2 * half]     + bb0 + 2.f * xin[m * CONCAT + n];
                val.y = acc[i][j][2 * half + 1] + bb1 + 2.f * xin[m * CONCAT + n + 1];
                *(float2*)&outz[m * CONCAT + n] = val;
            }
        }
    }
}

// ---------------- row-normalize ----------------
__global__ void k_norm(float* __restrict__ out) {
    int warp = threadIdx.x >> 5;
    int lane = threadIdx.x & 31;
    int row = blockIdx.x * 8 + warp;
    if (row >= 2 * BATCH) return;
    float* x = out + row * CONCAT;
    float vals[6];
    float ss = 0.f;
#pragma unroll
    for (int i = 0; i < 6; i++) { vals[i] = x[lane + 32 * i]; ss += vals[i] * vals[i]; }
#pragma unroll
    for (int o = 16; o; o >>= 1) ss += __shfl_xor_sync(0xffffffffu, ss, o);
    float s = 1.f / fmaxf(sqrtf(ss), 1e-12f);
#pragma unroll
    for (int i = 0; i < 6; i++) x[lane + 32 * i] = vals[i] * s;
}

// ---------------- launch ----------------
extern "C" void kernel_launch(void* const* d_in, const int* in_sizes, int n_in,
                              void* d_out, int out_size) {
    const float* emb       = (const float*)d_in[0];
    const float* cate_tab  = (const float*)d_in[1];
    const float* adj_vals  = (const float*)d_in[2];
    const float* mlp_ln_w  = (const float*)d_in[3];
    const float* mlp_ln_b  = (const float*)d_in[4];
    const float* mlp_w1    = (const float*)d_in[5];
    const float* mlp_b1    = (const float*)d_in[6];
    const float* mlp_w2    = (const float*)d_in[7];
    const float* mlp_b2    = (const float*)d_in[8];
    const int*   adj_rows  = (const int*)d_in[9];
    const int*   adj_cols  = (const int*)d_in[10];
    const int*   cates     = (const int*)d_in[11];
    const int*   cate_lens = (const int*)d_in[12];
    const int*   users     = (const int*)d_in[13];
    const int*   items     = (const int*)d_in[14];
    const int*   ihm       = (const int*)d_in[15];
    const int*   ihl       = (const int*)d_in[16];
    const int*   uhm       = (const int*)d_in[17];
    const int*   uhl       = (const int*)d_in[18];
    float* out = (float*)d_out;

    cudaFuncSetAttribute(k_gemm1_mma, cudaFuncAttributeMaxDynamicSharedMemorySize, G1_SMEM);
    cudaFuncSetAttribute(k_gemm2_mma, cudaFuncAttributeMaxDynamicSharedMemorySize, G2_SMEM);

    // CSR build
    k_zero_cnt<<<(N_NODES + 255) / 256, 256>>>();
    k_hist<<<(NNZ_E + 255) / 256, 256>>>(adj_rows);
    k_scan_block<<<SCAN_BLOCKS, 1024>>>();
    k_scan_tops<<<1, 256>>>();
    k_scan_add<<<(N_NODES + 255) / 256, 256>>>();
    k_scatter<<<(NNZ_E + 255) / 256, 256>>>(adj_rows, adj_cols, adj_vals);

    // fused: SpMM layer1 + mark + history features + weight split
    k_spmm1_fused<<<FUSED_GRID, 256>>>((const float2*)emb, emb, cate_tab, cates, cate_lens,
                                       users, items, ihm, ihl, uhm, uhl, mlp_w1, mlp_w2);
    // SpMM layer 2 (masked)
    k_spmm2<<<SPMM_B, 256>>>();
    // layer 3 at targets + static features
    k_e3static<<<(2 * BATCH * 32 + 255) / 256, 256>>>((const float2*)emb, users, items);

    // MLP on HMMA tensor cores
    k_ln<<<dim3(BATCH / 8, 4), 256>>>(mlp_ln_w, mlp_ln_b);
    k_gemm1_mma<<<dim3(BATCH / 128, INNER / 64, 4), 256, G1_SMEM>>>(mlp_b1);
    k_gemm2_mma<<<dim3(BATCH / 128, CONCAT / 64, 2), 256, G2_SMEM>>>(mlp_b2, out);
    k_norm<<<(2 * BATCH + 7) / 8, 256>>>(out);
}

// round 17
// speedup vs baseline: 1.1570x; 1.0296x over previous
#include <cuda_runtime.h>
#include <cuda_fp16.h>
#include <cstdint>

#define N_NODES   150000
#define NUM_USERS 100000
#define DIM       64
#define NNZ_E     2400000
#define BATCH     4096
#define HIST      50
#define UHIST     30
#define MC        5
#define CONCAT    192
#define INNER     384

#define SCAN_BLOCKS ((N_NODES + 1023) / 1024)   // 147

// fused spmm1 grid layout
#define SPMM_B  18750                 // ceil(150000*32/256)
#define MARK_O  (SPMM_B)              // 1024 blocks: 8 warps, 1 target/warp
#define UF_O    (MARK_O + 1024)       // 1024 blocks: 4 batch rows each
#define IF_O    (UF_O + 1024)
#define SW_O    (IF_O + 1024)         // 2304 blocks weight split
#define FUSED_GRID (SW_O + 2304)

// ---------------- device scratch ----------------
__device__ float g_l1[N_NODES * DIM];
__device__ float g_l2[N_NODES * DIM];
__device__ int   g_rowptr[N_NODES + 1];
__device__ int   g_wptr[N_NODES];
__device__ int   g_flag[N_NODES];
__device__ int   g_col[NNZ_E];
__device__ float g_val[NNZ_E];
__device__ int   g_bsum[256];
__device__ float g_uf[BATCH * CONCAT];
__device__ float g_itf[BATCH * CONCAT];
// fp16 split tensors
__device__ __align__(16) __half g_yhi[4 * BATCH * CONCAT];
__device__ __align__(16) __half g_ylo[4 * BATCH * CONCAT];
__device__ __align__(16) __half g_hhi[4 * BATCH * INNER];
__device__ __align__(16) __half g_hlo[4 * BATCH * INNER];
__device__ __align__(16) __half g_w1hi[4 * INNER * CONCAT];   // [v][n=384][k=192]
__device__ __align__(16) __half g_w1lo[4 * INNER * CONCAT];
__device__ __align__(16) __half g_w2hi[4 * CONCAT * INNER];   // [v][n=192][k=384]
__device__ __align__(16) __half g_w2lo[4 * CONCAT * INNER];

// ---------------- helpers ----------------
__device__ __forceinline__ uint32_t smem_u32(const void* p) {
    uint32_t a;
    asm("{ .reg .u64 t; cvta.to.shared.u64 t, %1; cvt.u32.u64 %0, t; }" : "=r"(a) : "l"(p));
    return a;
}
__device__ __forceinline__ void ldsm4(uint32_t& r0, uint32_t& r1, uint32_t& r2, uint32_t& r3,
                                      uint32_t addr) {
    asm volatile("ldmatrix.sync.aligned.m8n8.x4.shared.b16 {%0,%1,%2,%3}, [%4];"
                 : "=r"(r0), "=r"(r1), "=r"(r2), "=r"(r3) : "r"(addr));
}
__device__ __forceinline__ void mma16816(float* c, const uint32_t* a, const uint32_t* b) {
    asm volatile("mma.sync.aligned.m16n8k16.row.col.f32.f16.f16.f32 "
                 "{%0,%1,%2,%3},{%4,%5,%6,%7},{%8,%9},{%0,%1,%2,%3};"
                 : "+f"(c[0]), "+f"(c[1]), "+f"(c[2]), "+f"(c[3])
                 : "r"(a[0]), "r"(a[1]), "r"(a[2]), "r"(a[3]), "r"(b[0]), "r"(b[1]));
}
__device__ __forceinline__ void split2(float x, __half& hi, __half& lo) {
    hi = __float2half_rn(x);
    lo = __float2half_rn(x - __half2float(hi));
}

// ---------------- CSR build ----------------
__global__ void k_zero_cnt() {
    int i = blockIdx.x * blockDim.x + threadIdx.x;
    if (i < N_NODES) { g_wptr[i] = 0; g_flag[i] = 0; }
}
__global__ void k_hist(const int* __restrict__ rows) {
    int i = blockIdx.x * blockDim.x + threadIdx.x;
    if (i < NNZ_E) atomicAdd(&g_wptr[rows[i]], 1);
}
__global__ void k_scan_block() {
    __shared__ int s[1024];
    int tid = threadIdx.x;
    int i = blockIdx.x * 1024 + tid;
    int v = (i < N_NODES) ? g_wptr[i] : 0;
    s[tid] = v;
    __syncthreads();
    for (int off = 1; off < 1024; off <<= 1) {
        int t = (tid >= off) ? s[tid - off] : 0;
        __syncthreads();
        s[tid] += t;
        __syncthreads();
    }
    if (i < N_NODES) g_rowptr[i] = s[tid] - v;   // exclusive within block
    if (tid == 1023) g_bsum[blockIdx.x] = s[1023];
}
// merged scan_tops + scan_add: every block redundantly scans the 147 block sums
__global__ void k_scan_add2() {
    __shared__ int s[256];
    int tid = threadIdx.x;
    int v = (tid < SCAN_BLOCKS) ? g_bsum[tid] : 0;
    s[tid] = v;
    __syncthreads();
    for (int off = 1; off < 256; off <<= 1) {
        int t = (tid >= off) ? s[tid - off] : 0;
        __syncthreads();
        s[tid] += t;
        __syncthreads();
    }
    int i = blockIdx.x * blockDim.x + tid;
    if (i < N_NODES) {
        int blk = i >> 10;
        int add = (blk > 0) ? s[blk - 1] : 0;
        int r = g_rowptr[i] + add;
        g_rowptr[i] = r;
        g_wptr[i] = r;
    }
    if (i == 0) g_rowptr[N_NODES] = NNZ_E;
}
__global__ void k_scatter(const int* __restrict__ rows, const int* __restrict__ cols,
                          const float* __restrict__ vals) {
    int i = blockIdx.x * blockDim.x + threadIdx.x;
    if (i < NNZ_E) {
        int r = rows[i];
        int pos = atomicAdd(&g_wptr[r], 1);
        g_col[pos] = cols[i];
        g_val[pos] = vals[i];
    }
}

// ---------------- SpMM core (warp computes one row) ----------------
__device__ __forceinline__ float2 spmm_row(const float2* __restrict__ src, int row, int lane) {
    int s = g_rowptr[row], e = g_rowptr[row + 1];
    float2 a = make_float2(0.f, 0.f);
    int j = s;
    for (; j + 3 < e; j += 4) {
        int c0 = g_col[j], c1 = g_col[j + 1], c2 = g_col[j + 2], c3 = g_col[j + 3];
        float v0 = g_val[j], v1 = g_val[j + 1], v2 = g_val[j + 2], v3 = g_val[j + 3];
        float2 x0 = src[c0 * 32 + lane];
        float2 x1 = src[c1 * 32 + lane];
        float2 x2 = src[c2 * 32 + lane];
        float2 x3 = src[c3 * 32 + lane];
        a.x += v0 * x0.x; a.y += v0 * x0.y;
        a.x += v1 * x1.x; a.y += v1 * x1.y;
        a.x += v2 * x2.x; a.y += v2 * x2.y;
        a.x += v3 * x3.x; a.y += v3 * x3.y;
    }
    for (; j < e; j++) {
        int c = g_col[j];
        float v = g_val[j];
        float2 x = src[c * 32 + lane];
        a.x += v * x.x; a.y += v * x.y;
    }
    return a;
}

// ---------------- FUSED: spmm layer1 + mark + history features + weight split ----------------
__global__ void k_spmm1_fused(const float2* __restrict__ emb2,
                              const float* __restrict__ emb,
                              const float* __restrict__ cate_tab,
                              const int* __restrict__ cates, const int* __restrict__ clens,
                              const int* __restrict__ users, const int* __restrict__ items,
                              const int* __restrict__ ihm, const int* __restrict__ ihl,
                              const int* __restrict__ uhm, const int* __restrict__ uhl,
                              const float* __restrict__ w1, const float* __restrict__ w2) {
    int blk = blockIdx.x;
    int tid = threadIdx.x;

    if (blk < SPMM_B) {
        int gtid = blk * 256 + tid;
        int row = gtid >> 5;
        int lane = gtid & 31;
        if (row >= N_NODES) return;
        float2 a = spmm_row(emb2, row, lane);
        ((float2*)g_l1)[row * 32 + lane] = a;
    } else if (blk < UF_O) {
        int t = (blk - MARK_O) * 8 + (tid >> 5);
        int lane = tid & 31;
        int row = (t < BATCH) ? users[t] : (NUM_USERS + items[t - BATCH]);
        if (lane == 0) g_flag[row] = 1;
        int s = g_rowptr[row], e = g_rowptr[row + 1];
        for (int j = s + lane; j < e; j += 32) g_flag[g_col[j]] = 1;
    } else if (blk < IF_O) {
        int b = (blk - UF_O) * 4 + (tid >> 6);
        int d = tid & 63;
        int len = ihl[b];
        float si = 0.f, sc = 0.f;
        for (int h = 0; h < len; h++) {
            int it = ihm[b * HIST + h];
            si += emb[(it + NUM_USERS) * DIM + d];
            int cl = clens[it];
            float cs = 0.f;
            for (int c = 0; c < cl; c++)
                cs += cate_tab[cates[it * MC + c] * DIM + d];
            sc += cs / ((float)cl + 1e-9f);
        }
        float inv = 1.f / ((float)len + 1e-9f);
        g_uf[b * CONCAT + DIM + d]      = si * inv;
        g_uf[b * CONCAT + 2 * DIM + d]  = sc * inv;
    } else if (blk < SW_O) {
        int b = (blk - IF_O) * 4 + (tid >> 6);
        int d = tid & 63;
        int it = items[b];
        int cl = clens[it];
        float cs = 0.f;
        for (int c = 0; c < cl; c++)
            cs += cate_tab[cates[it * MC + c] * DIM + d];
        float avg_ic = cs / ((float)cl + 1e-9f);
        int len = uhl[b];
        float sh = 0.f;
        for (int h = 0; h < len; h++)
            sh += emb[uhm[b * UHIST + h] * DIM + d];
        g_itf[b * CONCAT + DIM + d]     = avg_ic;
        g_itf[b * CONCAT + 2 * DIM + d] = sh / ((float)len + 1e-9f);
    } else {
        int i = (blk - SW_O) * 256 + tid;
        const int C1 = 4 * INNER * CONCAT;
        if (i < C1) {
            int v = i / (INNER * CONCAT);
            int rem = i % (INNER * CONCAT);
            int n = rem / CONCAT;
            int k = rem % CONCAT;
            float x = w1[v * CONCAT * INNER + k * INNER + n];
            __half hi, lo; split2(x, hi, lo);
            g_w1hi[i] = hi; g_w1lo[i] = lo;
        } else if (i < 2 * C1) {
            int j = i - C1;
            int v = j / (CONCAT * INNER);
            int rem = j % (CONCAT * INNER);
            int n = rem / INNER;
            int k = rem % INNER;
            float x = w2[v * INNER * CONCAT + k * CONCAT + n];
            __half hi, lo; split2(x, hi, lo);
            g_w2hi[j] = hi; g_w2lo[j] = lo;
        }
    }
}

// ---------------- SpMM layer 2 (masked) ----------------
__global__ void k_spmm2() {
    int gtid = blockIdx.x * blockDim.x + threadIdx.x;
    int row = gtid >> 5;
    int lane = gtid & 31;
    if (row >= N_NODES) return;
    if (!g_flag[row]) return;
    float2 a = spmm_row((const float2*)g_l1, row, lane);
    ((float2*)g_l2)[row * 32 + lane] = a;
}

// ---------------- FUSED: layer-3 at targets + static feature + layernorm ----------------
__global__ void k_e3ln(const float2* __restrict__ emb2,
                       const int* __restrict__ users, const int* __restrict__ items,
                       const float* __restrict__ ln_w, const float* __restrict__ ln_b) {
    int gtid = blockIdx.x * blockDim.x + threadIdx.x;
    int t = gtid >> 5;
    int lane = gtid & 31;
    if (t >= 2 * BATCH) return;
    int row = (t < BATCH) ? users[t] : (NUM_USERS + items[t - BATCH]);
    float2 a = spmm_row((const float2*)g_l2, row, lane);
    int o = row * 32 + lane;
    float2 e0 = emb2[o];
    float2 e1 = ((const float2*)g_l1)[o];
    float2 e2 = ((const float2*)g_l2)[o];
    float2 r;
    r.x = (e0.x + e1.x + e2.x + a.x) * 0.25f;
    r.y = (e0.y + e1.y + e2.y + a.y) * 0.25f;

    int brow = (t < BATCH) ? t : (t - BATCH);
    float* feat = (t < BATCH) ? g_uf : g_itf;
    // store static feature (needed for the gemm2 residual)
    ((float2*)feat)[brow * (CONCAT / 2) + lane] = r;
    // load history cols (written in the spmm1_fused launch)
    float2 h1 = *(const float2*)&feat[brow * CONCAT + DIM + 2 * lane];
    float2 h2 = *(const float2*)&feat[brow * CONCAT + 2 * DIM + 2 * lane];

    float vals[6] = { r.x, r.y, h1.x, h1.y, h2.x, h2.y };
    float s = vals[0] + vals[1] + vals[2] + vals[3] + vals[4] + vals[5];
#pragma unroll
    for (int off = 16; off; off >>= 1) s += __shfl_xor_sync(0xffffffffu, s, off);
    float mu = s * (1.f / CONCAT);
    float vv = 0.f;
#pragma unroll
    for (int i = 0; i < 6; i++) { float d = vals[i] - mu; vv += d * d; }
#pragma unroll
    for (int off = 16; off; off >>= 1) vv += __shfl_xor_sync(0xffffffffu, vv, off);
    float rs = rsqrtf(vv * (1.f / CONCAT) + 1e-5f);

    int cols[3] = { 2 * lane, DIM + 2 * lane, 2 * DIM + 2 * lane };
    int v0 = (t < BATCH) ? 0 : 2;
#pragma unroll
    for (int vi = 0; vi < 2; vi++) {
        int v = v0 + vi;
        int base = v * (BATCH * CONCAT) + brow * CONCAT;
#pragma unroll
        for (int p = 0; p < 3; p++) {
            int c = cols[p];
            float y0 = (vals[2 * p]     - mu) * rs * ln_w[v * CONCAT + c]     + ln_b[v * CONCAT + c];
            float y1 = (vals[2 * p + 1] - mu) * rs * ln_w[v * CONCAT + c + 1] + ln_b[v * CONCAT + c + 1];
            __half h0, l0, h1h, l1h;
            split2(y0, h0, l0);
            split2(y1, h1h, l1h);
            *(__half2*)&g_yhi[base + c] = __halves2half2(h0, h1h);
            *(__half2*)&g_ylo[base + c] = __halves2half2(l0, l1h);
        }
    }
}

// ---------------- HMMA GEMM1: H = relu(Y @ W1 + b1), K chunked for 2 CTAs/SM ----------------
// chunk = 96 cols (12 x 8 halves), row stride 208B. Ah@0 Al@26624 Bh@53248 Bl@79872.
#define G1_SMEM 106496
__global__ __launch_bounds__(256, 2) void k_gemm1_mma(const float* __restrict__ b1) {
    extern __shared__ __align__(16) char smem[];
    int tid = threadIdx.x, w = tid >> 5, lane = tid & 31;
    int v = blockIdx.z;
    int m0 = blockIdx.x * 128, n0 = blockIdx.y * 128;

    const __half* Ahg = g_yhi + v * (BATCH * CONCAT);
    const __half* Alg = g_ylo + v * (BATCH * CONCAT);
    const __half* Bhg = g_w1hi + v * (INNER * CONCAT);
    const __half* Blg = g_w1lo + v * (INNER * CONCAT);

    uint32_t sb = smem_u32(smem);
    int wm = (w >> 2) * 64, wn = (w & 3) * 32;
    float acc[4][4][4];
#pragma unroll
    for (int i = 0; i < 4; i++)
#pragma unroll
        for (int j = 0; j < 4; j++)
#pragma unroll
            for (int c = 0; c < 4; c++) acc[i][j][c] = 0.f;

    int lr = lane & 15;
    int lk2 = ((lane >> 4) * 8) * 2;

#pragma unroll 1
    for (int ch = 0; ch < 2; ch++) {
        if (ch) __syncthreads();
        int kl = ch * 96;
        for (int idx = tid; idx < 128 * 12; idx += 256) {
            int r = idx / 12, c8 = idx % 12;
            int d = r * 208 + c8 * 16;
            *(uint4*)(smem + d)         = *(const uint4*)(Ahg + (m0 + r) * CONCAT + kl + c8 * 8);
            *(uint4*)(smem + 26624 + d) = *(const uint4*)(Alg + (m0 + r) * CONCAT + kl + c8 * 8);
            *(uint4*)(smem + 53248 + d) = *(const uint4*)(Bhg + (n0 + r) * CONCAT + kl + c8 * 8);
            *(uint4*)(smem + 79872 + d) = *(const uint4*)(Blg + (n0 + r) * CONCAT + kl + c8 * 8);
        }
        __syncthreads();

#pragma unroll 1
        for (int ks = 0; ks < 6; ks++) {
            int k2 = ks * 32 + lk2;
            uint32_t ah[4][4], al[4][4], bh[4][2], bl[4][2];
#pragma unroll
            for (int i = 0; i < 4; i++) {
                uint32_t a = sb + (wm + 16 * i + lr) * 208 + k2;
                ldsm4(ah[i][0], ah[i][1], ah[i][2], ah[i][3], a);
                ldsm4(al[i][0], al[i][1], al[i][2], al[i][3], a + 26624);
            }
#pragma unroll
            for (int j2 = 0; j2 < 2; j2++) {
                uint32_t a = sb + 53248 + (wn + 16 * j2 + lr) * 208 + k2;
                uint32_t r0, r1, r2, r3;
                ldsm4(r0, r1, r2, r3, a);
                bh[2 * j2][0] = r0; bh[2 * j2][1] = r2;
                bh[2 * j2 + 1][0] = r1; bh[2 * j2 + 1][1] = r3;
                ldsm4(r0, r1, r2, r3, a + 26624);
                bl[2 * j2][0] = r0; bl[2 * j2][1] = r2;
                bl[2 * j2 + 1][0] = r1; bl[2 * j2 + 1][1] = r3;
            }
#pragma unroll
            for (int i = 0; i < 4; i++)
#pragma unroll
                for (int j = 0; j < 4; j++) {
                    mma16816(acc[i][j], ah[i], bh[j]);
                    mma16816(acc[i][j], ah[i], bl[j]);
                    mma16816(acc[i][j], al[i], bh[j]);
                }
        }
    }

    int r0 = lane >> 2, c0 = (lane & 3) * 2;
    __half* Hh = g_hhi + v * (BATCH * INNER);
    __half* Hl = g_hlo + v * (BATCH * INNER);
#pragma unroll
    for (int i = 0; i < 4; i++) {
#pragma unroll
        for (int j = 0; j < 4; j++) {
            int n = n0 + wn + 8 * j + c0;
            float bb0 = b1[v * INNER + n], bb1 = b1[v * INNER + n + 1];
#pragma unroll
            for (int half = 0; half < 2; half++) {
                int m = m0 + wm + 16 * i + r0 + 8 * half;
                float x0 = fmaxf(acc[i][j][2 * half] + bb0, 0.f);
                float x1 = fmaxf(acc[i][j][2 * half + 1] + bb1, 0.f);
                __half h0, l0, h1, l1;
                split2(x0, h0, l0);
                split2(x1, h1, l1);
                *(__half2*)(Hh + m * INNER + n) = __halves2half2(h0, h1);
                *(__half2*)(Hl + m * INNER + n) = __halves2half2(l0, l1);
            }
        }
    }
}

// ---------------- HMMA GEMM2: out = sum_v H_v @ W2_v + b2 + 2x, K chunked ----------------
// chunk = 96 cols, 8 chunks (2 variants x 384). Ah@0 Al@26624 Bh@53248 Bl@66560.
#define G2_SMEM 79872
__global__ __launch_bounds__(256, 2) void k_gemm2_mma(const float* __restrict__ b2,
                                                      float* __restrict__ out) {
    extern __shared__ __align__(16) char smem[];
    int tid = threadIdx.x, w = tid >> 5, lane = tid & 31;
    int z = blockIdx.z;
    int v0 = 2 * z;
    int m0 = blockIdx.x * 128, n0 = blockIdx.y * 64;

    uint32_t sb = smem_u32(smem);
    int wm = (w & 3) * 32, wn = (w >> 2) * 32;
    float acc[2][4][4];
#pragma unroll
    for (int i = 0; i < 2; i++)
#pragma unroll
        for (int j = 0; j < 4; j++)
#pragma unroll
            for (int c = 0; c < 4; c++) acc[i][j][c] = 0.f;

    int lr = lane & 15;
    int lk2 = ((lane >> 4) * 8) * 2;

#pragma unroll 1
    for (int cc = 0; cc < 8; cc++) {
        int v = v0 + (cc >> 2);
        int kl = (cc & 3) * 96;
        const __half* Ahg = g_hhi + v * (BATCH * INNER);
        const __half* Alg = g_hlo + v * (BATCH * INNER);
        const __half* Bhg = g_w2hi + v * (CONCAT * INNER);
        const __half* Blg = g_w2lo + v * (CONCAT * INNER);
        if (cc) __syncthreads();
        for (int idx = tid; idx < 128 * 12; idx += 256) {
            int r = idx / 12, c8 = idx % 12;
            int d = r * 208 + c8 * 16;
            *(uint4*)(smem + d)         = *(const uint4*)(Ahg + (m0 + r) * INNER + kl + c8 * 8);
            *(uint4*)(smem + 26624 + d) = *(const uint4*)(Alg + (m0 + r) * INNER + kl + c8 * 8);
        }
        for (int idx = tid; idx < 64 * 12; idx += 256) {
            int r = idx / 12, c8 = idx % 12;
            int d = r * 208 + c8 * 16;
            *(uint4*)(smem + 53248 + d) = *(const uint4*)(Bhg + (n0 + r) * INNER + kl + c8 * 8);
            *(uint4*)(smem + 66560 + d) = *(const uint4*)(Blg + (n0 + r) * INNER + kl + c8 * 8);
        }
        __syncthreads();

#pragma unroll 1
        for (int ks = 0; ks < 6; ks++) {
            int k2 = ks * 32 + lk2;
            uint32_t ah[2][4], al[2][4], bh[4][2], bl[4][2];
#pragma unroll
            for (int i = 0; i < 2; i++) {
                uint32_t a = sb + (wm + 16 * i + lr) * 208 + k2;
                ldsm4(ah[i][0], ah[i][1], ah[i][2], ah[i][3], a);
                ldsm4(al[i][0], al[i][1], al[i][2], al[i][3], a + 26624);
            }
#pragma unroll
            for (int j2 = 0; j2 < 2; j2++) {
                uint32_t a = sb + 53248 + (wn + 16 * j2 + lr) * 208 + k2;
                uint32_t r0, r1, r2, r3;
                ldsm4(r0, r1, r2, r3, a);
                bh[2 * j2][0] = r0; bh[2 * j2][1] = r2;
                bh[2 * j2 + 1][0] = r1; bh[2 * j2 + 1][1] = r3;
                ldsm4(r0, r1, r2, r3, a + 13312);
                bl[2 * j2][0] = r0; bl[2 * j2][1] = r2;
                bl[2 * j2 + 1][0] = r1; bl[2 * j2 + 1][1] = r3;
            }
#pragma unroll
            for (int i = 0; i < 2; i++)
#pragma unroll
                for (int j = 0; j < 4; j++) {
                    mma16816(acc[i][j], ah[i], bh[j]);
                    mma16816(acc[i][j], ah[i], bl[j]);
                    mma16816(acc[i][j], al[i], bh[j]);
                }
        }
    }

    int r0 = lane >> 2, c0 = (lane & 3) * 2;
    const float* xin = (z == 0) ? g_uf : g_itf;
    float* outz = out + z * (BATCH * CONCAT);
#pragma unroll
    for (int i = 0; i < 2; i++) {
#pragma unroll
        for (int j = 0; j < 4; j++) {
            int n = n0 + wn + 8 * j + c0;
            float bb0 = b2[v0 * CONCAT + n]     + b2[(v0 + 1) * CONCAT + n];
            float bb1 = b2[v0 * CONCAT + n + 1] + b2[(v0 + 1) * CONCAT + n + 1];
#pragma unroll
            for (int half = 0; half < 2; half++) {
                int m = m0 + wm + 16 * i + r0 + 8 * half;
                float2 val;
                val.x = acc[i][j][2 * half]     + bb0 + 2.f * xin[m * CONCAT + n];
                val.y = acc[i][j][2 * half + 1] + bb1 + 2.f * xin[m * CONCAT + n + 1];
                *(float2*)&outz[m * CONCAT + n] = val;
            }
        }
    }
}

// ---------------- row-normalize ----------------
__global__ void k_norm(float* __restrict__ out) {
    int warp = threadIdx.x >> 5;
    int lane = threadIdx.x & 31;
    int row = blockIdx.x * 8 + warp;
    if (row >= 2 * BATCH) return;
    float* x = out + row * CONCAT;
    float vals[6];
    float ss = 0.f;
#pragma unroll
    for (int i = 0; i < 6; i++) { vals[i] = x[lane + 32 * i]; ss += vals[i] * vals[i]; }
#pragma unroll
    for (int o = 16; o; o >>= 1) ss += __shfl_xor_sync(0xffffffffu, ss, o);
    float s = 1.f / fmaxf(sqrtf(ss), 1e-12f);
#pragma unroll
    for (int i = 0; i < 6; i++) x[lane + 32 * i] = vals[i] * s;
}

// ---------------- launch ----------------
extern "C" void kernel_launch(void* const* d_in, const int* in_sizes, int n_in,
                              void* d_out, int out_size) {
    const float* emb       = (const float*)d_in[0];
    const float* cate_tab  = (const float*)d_in[1];
    const float* adj_vals  = (const float*)d_in[2];
    const float* mlp_ln_w  = (const float*)d_in[3];
    const float* mlp_ln_b  = (const float*)d_in[4];
    const float* mlp_w1    = (const float*)d_in[5];
    const float* mlp_b1    = (const float*)d_in[6];
    const float* mlp_w2    = (const float*)d_in[7];
    const float* mlp_b2    = (const float*)d_in[8];
    const int*   adj_rows  = (const int*)d_in[9];
    const int*   adj_cols  = (const int*)d_in[10];
    const int*   cates     = (const int*)d_in[11];
    const int*   cate_lens = (const int*)d_in[12];
    const int*   users     = (const int*)d_in[13];
    const int*   items     = (const int*)d_in[14];
    const int*   ihm       = (const int*)d_in[15];
    const int*   ihl       = (const int*)d_in[16];
    const int*   uhm       = (const int*)d_in[17];
    const int*   uhl       = (const int*)d_in[18];
    float* out = (float*)d_out;

    cudaFuncSetAttribute(k_gemm1_mma, cudaFuncAttributeMaxDynamicSharedMemorySize, G1_SMEM);
    cudaFuncSetAttribute(k_gemm2_mma, cudaFuncAttributeMaxDynamicSharedMemorySize, G2_SMEM);

    // CSR build (scan_tops merged into scan_add)
    k_zero_cnt<<<(N_NODES + 255) / 256, 256>>>();
    k_hist<<<(NNZ_E + 255) / 256, 256>>>(adj_rows);
    k_scan_block<<<SCAN_BLOCKS, 1024>>>();
    k_scan_add2<<<(N_NODES + 255) / 256, 256>>>();
    k_scatter<<<(NNZ_E + 255) / 256, 256>>>(adj_rows, adj_cols, adj_vals);

    // fused: SpMM layer1 + mark + history features + weight split
    k_spmm1_fused<<<FUSED_GRID, 256>>>((const float2*)emb, emb, cate_tab, cates, cate_lens,
                                       users, items, ihm, ihl, uhm, uhl, mlp_w1, mlp_w2);
    // SpMM layer 2 (masked)
    k_spmm2<<<SPMM_B, 256>>>();
    // layer 3 at targets + static features + layernorm (fused)
    k_e3ln<<<(2 * BATCH * 32 + 255) / 256, 256>>>((const float2*)emb, users, items,
                                                  mlp_ln_w, mlp_ln_b);

    // MLP on HMMA tensor cores
    k_gemm1_mma<<<dim3(BATCH / 128, INNER / 128, 4), 256, G1_SMEM>>>(mlp_b1);
    k_gemm2_mma<<<dim3(BATCH / 128, CONCAT / 64, 2), 256, G2_SMEM>>>(mlp_b2, out);
    k_norm<<<(2 * BATCH + 7) / 8, 256>>>(out);
}